// round 13
// baseline (speedup 1.0000x reference)
#include <cuda_runtime.h>
#include <cuda_fp16.h>
#include <math.h>
#include <stdint.h>

#define BB 64
#define NN 1025
#define DD 384
#define KKB 8
#define HH 128
#define CIN 1152
#define OUTD 384
#define NSC 8

__device__ float g_cls[BB * DD];
__device__ float g_part[BB * NSC * 2 * DD];
__device__ float g_U[DD * 128];
__device__ float g_V[DD * 128];
__device__ float g_nrm[KKB];
__device__ float g_P[128 * 128];
__device__ float g_T0[128 * OUTD];
__device__ float g_s[BB * KKB];
__device__ float g_g2[BB];
__device__ float g_lg[BB];
__device__ float g_scale[BB * OUTD];
__device__ float g_Sinv[BB * 128 * 128];
__device__ float g_E[BB * DD * 128];
__device__ __half g_WTh[(size_t)BB * OUTD * DD];
__device__ __half g_lmh[(size_t)BB * NN * DD + 127 * DD];

__device__ __forceinline__ uint32_t smem_u32(const void* p) {
    return (uint32_t)__cvta_generic_to_shared(p);
}

__global__ void __launch_bounds__(384) k_stats(const float* __restrict__ x) {
    int b = blockIdx.x, c = blockIdx.y, d = threadIdx.x;
    const float* xb = x + (size_t)b * NN * DD + d;
    float s = 0.f, s2 = 0.f;
    int n0 = c * 128;
    #pragma unroll 4
    for (int r = 0; r < 128; r++) {
        float v = xb[(size_t)(n0 + r) * DD];
        s += v; s2 += v * v;
    }
    if (c == NSC - 1) {
        float v = xb[(size_t)1024 * DD];
        s += v; s2 += v * v;
    }
    if (c == 0) g_cls[b * DD + d] = xb[0];
    g_part[((b * NSC + c) * 2 + 0) * DD + d] = s;
    g_part[((b * NSC + c) * 2 + 1) * DD + d] = s2;
}

__global__ void k_prep(const float* __restrict__ Lb, const float* __restrict__ Rb) {
    int bid = blockIdx.x;
    if (bid < 192) {
        int idx = bid * 256 + threadIdx.x;
        int d = idx >> 7, j = idx & 127, k = j >> 4, t = j & 15;
        if (t < 8) {
            g_U[d * 128 + j] = Lb[(k * DD + d) * 8 + t];
            g_V[d * 128 + j] = Rb[(k * DD + d) * 8 + t];
        } else {
            g_U[d * 128 + j] = -Rb[(k * DD + d) * 8 + t - 8];
            g_V[d * 128 + j] =  Lb[(k * DD + d) * 8 + t - 8];
        }
    } else {
        int k = bid - 192, t = threadIdx.x;
        int which = t / 64, e = t % 64, i = e / 8, j = e % 8;
        __shared__ float gm[3][8][8];
        __shared__ float red[192];
        if (t < 192) {
            const float* Ap = (which == 0) ? Lb : Rb;
            const float* Bp = (which == 1) ? Rb : Lb;
            float acc = 0.f;
            #pragma unroll 8
            for (int d = 0; d < DD; d++)
                acc += Ap[(k * DD + d) * 8 + i] * Bp[(k * DD + d) * 8 + j];
            gm[which][i][j] = acc;
        }
        __syncthreads();
        float part = 0.f;
        if (t < 64) part = 2.f * (gm[0][i][j] * gm[1][i][j] - gm[2][i][j] * gm[2][j][i]);
        if (t < 192) red[t] = part;
        __syncthreads();
        if (t == 0) {
            float s = 0.f;
            for (int q = 0; q < 64; q++) s += red[q];
            g_nrm[k] = fmaxf(sqrtf(s), 1e-6f);
        }
    }
}

__global__ void __launch_bounds__(256) k_PT0(const float* __restrict__ W) {
    int bid = blockIdx.x;
    int tid = threadIdx.x;
    if (bid < 4) {
        int i0 = (bid >> 1) * 64, j0 = (bid & 1) * 64;
        __shared__ float As[16][68];
        __shared__ float Bs[16][68];
        int tx = tid & 15, ty = tid >> 4;
        int r = tid >> 4, c4 = (tid & 15) * 4;
        float acc[4][4] = {};
        for (int k0 = 0; k0 < DD; k0 += 16) {
            *(float4*)&As[r][c4] = *(const float4*)(g_V + (size_t)(k0 + r) * 128 + i0 + c4);
            *(float4*)&Bs[r][c4] = *(const float4*)(g_U + (size_t)(k0 + r) * 128 + j0 + c4);
            __syncthreads();
            #pragma unroll
            for (int kk = 0; kk < 16; kk++) {
                float av[4], bv[4];
                #pragma unroll
                for (int i = 0; i < 4; i++) av[i] = As[kk][ty * 4 + i];
                #pragma unroll
                for (int j = 0; j < 4; j++) bv[j] = Bs[kk][tx * 4 + j];
                #pragma unroll
                for (int i = 0; i < 4; i++)
                    #pragma unroll
                    for (int j = 0; j < 4; j++) acc[i][j] += av[i] * bv[j];
            }
            __syncthreads();
        }
        #pragma unroll
        for (int i = 0; i < 4; i++)
            *(float4*)(g_P + (size_t)(i0 + ty * 4 + i) * 128 + j0 + tx * 4) = *(float4*)acc[i];
    } else {
        int b2 = bid - 4;
        int o0 = (b2 % 3) * 128, j0 = (b2 / 3) * 32;
        __shared__ float As2[16][36];
        __shared__ float Bs2[16][132];
        int tx = tid & 31, ty = tid >> 5;
        int ro = tid >> 1, co = tid & 1;
        int ja = tid & 31, ka = tid >> 5;
        float acc[4][4] = {};
        for (int k0 = 0; k0 < DD; k0 += 16) {
            As2[ka][ja]     = g_V[(size_t)(k0 + ka) * 128 + j0 + ja];
            As2[ka + 8][ja] = g_V[(size_t)(k0 + ka + 8) * 128 + j0 + ja];
            #pragma unroll
            for (int h = 0; h < 2; h++) {
                float4 w = *(const float4*)(W + (size_t)(o0 + ro) * DD + k0 + co * 8 + h * 4);
                Bs2[co * 8 + h * 4 + 0][ro] = w.x;
                Bs2[co * 8 + h * 4 + 1][ro] = w.y;
                Bs2[co * 8 + h * 4 + 2][ro] = w.z;
                Bs2[co * 8 + h * 4 + 3][ro] = w.w;
            }
            __syncthreads();
            #pragma unroll
            for (int kk = 0; kk < 16; kk++) {
                float av[4], bv[4];
                #pragma unroll
                for (int i = 0; i < 4; i++) av[i] = As2[kk][ty * 4 + i];
                #pragma unroll
                for (int j = 0; j < 4; j++) bv[j] = Bs2[kk][tx * 4 + j];
                #pragma unroll
                for (int i = 0; i < 4; i++)
                    #pragma unroll
                    for (int j = 0; j < 4; j++) acc[i][j] += av[i] * bv[j];
            }
            __syncthreads();
        }
        #pragma unroll
        for (int i = 0; i < 4; i++)
            *(float4*)(g_T0 + (size_t)(j0 + ty * 4 + i) * OUTD + o0 + tx * 4) = *(float4*)acc[i];
    }
}

__global__ void __launch_bounds__(512) k_ctrl(
        const float* __restrict__ w1, const float* __restrict__ b1,
        const float* __restrict__ w_rot, const float* __restrict__ b_rot,
        const float* __restrict__ w_rg, const float* __restrict__ b_rg,
        const float* __restrict__ w_lg, const float* __restrict__ b_lg,
        const float* __restrict__ w_sc, const float* __restrict__ b_sc,
        const float* __restrict__ scale_basis, const float* __restrict__ ss_ptr) {
    int b = blockIdx.x, t = threadIdx.x;
    int lane = t & 31, wid = t >> 5;
    __shared__ float zs[CIN];
    __shared__ float hs[HH];
    __shared__ float coef[KKB];
    const float inv_n = 1.f / (float)NN;
    if (t < DD) {
        float s = 0.f, s2 = 0.f;
        #pragma unroll
        for (int c = 0; c < NSC; c++) {
            s  += g_part[((b * NSC + c) * 2 + 0) * DD + t];
            s2 += g_part[((b * NSC + c) * 2 + 1) * DD + t];
        }
        float mean = s * inv_n;
        zs[t] = g_cls[b * DD + t];
        zs[384 + t] = mean;
        zs[768 + t] = s2 * inv_n - mean * mean;
    }
    __syncthreads();
    for (int to = wid; to < HH; to += 16) {
        const float* w = w1 + (size_t)to * CIN;
        float acc = 0.f;
        for (int c = lane; c < CIN; c += 32) acc += zs[c] * w[c];
        #pragma unroll
        for (int off = 16; off; off >>= 1) acc += __shfl_down_sync(0xFFFFFFFFu, acc, off);
        if (lane == 0) {
            float xg = acc + b1[to];
            float x3 = xg * xg * xg;
            hs[to] = 0.5f * xg * (1.f + tanhf(0.7978845608028654f * (xg + 0.044715f * x3)));
        }
    }
    __syncthreads();
    if (t < 8) {
        float acc = b_rot[t];
        for (int c = 0; c < HH; c++) acc += hs[c] * w_rot[t * HH + c];
        g_s[b * 8 + t] = 0.5f * tanhf(acc) / g_nrm[t];
    } else if (t == 8) {
        float acc = b_rg[0];
        for (int c = 0; c < HH; c++) acc += hs[c] * w_rg[c];
        g_g2[b] = 2.f / (1.f + expf(-acc));
    } else if (t == 9) {
        float acc = b_lg[0];
        for (int c = 0; c < HH; c++) acc += hs[c] * w_lg[c];
        g_lg[b] = 1.f / (1.f + expf(-acc));
    } else if (t >= 16 && t < 24) {
        int k = t - 16;
        float acc = b_sc[k];
        for (int c = 0; c < HH; c++) acc += hs[c] * w_sc[k * HH + c];
        coef[k] = tanhf(acc);
    }
    __syncthreads();
    float ss = ss_ptr[0];
    if (t < OUTD) {
        float acc = 0.f;
        for (int k = 0; k < KKB; k++) acc += coef[k] * scale_basis[k * OUTD + t];
        g_scale[b * OUTD + t] = 1.f + ss * tanhf(acc);
    }
}

#define LUP 129
#define LUSOLVE_SMEM (2 * 128 * LUP * 4)
__global__ void __launch_bounds__(128) k_lusolve() {
    extern __shared__ float smf[];
    float* a = smf;
    float* y = smf + 128 * LUP;
    __shared__ float sb[8];
    int b = blockIdx.x, i = threadIdx.x;
    if (i < 8) sb[i] = g_s[b * 8 + i];
    __syncthreads();
    for (int q = 0; q < 128; q++)
        a[i * LUP + q] = (i == q ? 1.f : 0.f) - g_P[i * 128 + q] * sb[q >> 4];
    for (int p = 0; p < 127; p++) {
        __syncthreads();
        if (i > p) {
            float l = a[i * LUP + p] / a[p * LUP + p];
            a[i * LUP + p] = l;
            for (int q = p + 1; q < 128; q++) a[i * LUP + q] -= l * a[p * LUP + q];
        }
    }
    __syncthreads();
    for (int p = 0; p < 128; p++) {
        float a0 = 0.f, a1 = 0.f, a2 = 0.f, a3 = 0.f;
        const float* row = a + p * LUP;
        int q = 0;
        for (; q + 3 < p; q += 4) {
            a0 += row[q] * y[q * LUP + i];
            a1 += row[q + 1] * y[(q + 1) * LUP + i];
            a2 += row[q + 2] * y[(q + 2) * LUP + i];
            a3 += row[q + 3] * y[(q + 3) * LUP + i];
        }
        for (; q < p; q++) a0 += row[q] * y[q * LUP + i];
        y[p * LUP + i] = ((p == i) ? 1.f : 0.f) - (a0 + a1) - (a2 + a3);
    }
    for (int p = 127; p >= 0; p--) {
        float a0 = 0.f, a1 = 0.f, a2 = 0.f, a3 = 0.f;
        const float* row = a + p * LUP;
        int q = p + 1;
        for (; q + 3 < 128; q += 4) {
            a0 += row[q] * y[q * LUP + i];
            a1 += row[q + 1] * y[(q + 1) * LUP + i];
            a2 += row[q + 2] * y[(q + 2) * LUP + i];
            a3 += row[q + 3] * y[(q + 3) * LUP + i];
        }
        for (; q < 128; q++) a0 += row[q] * y[q * LUP + i];
        y[p * LUP + i] = (y[p * LUP + i] - (a0 + a1) - (a2 + a3)) / row[p];
    }
    float* sv = g_Sinv + (size_t)b * 128 * 128;
    for (int p = 0; p < 128; p++)
        sv[p * 128 + i] = sb[p >> 4] * y[p * LUP + i];
}

__global__ void __launch_bounds__(256) k_E() {
    int b = blockIdx.z, d0 = blockIdx.y * 128;
    __shared__ __align__(16) float As[16][132];
    __shared__ __align__(16) float Bs[16][132];
    int tid = threadIdx.x, tx = tid & 15, ty = tid >> 4;
    const float* Sv = g_Sinv + (size_t)b * 128 * 128;
    float acc[8][8] = {};
    int ar = tid >> 2, ac = (tid & 3) * 4;
    for (int k0 = 0; k0 < 128; k0 += 16) {
        #pragma unroll
        for (int h = 0; h < 2; h++) {
            int d = d0 + ar + h * 64;
            float4 v = *(const float4*)(g_U + (size_t)d * 128 + k0 + ac);
            As[ac + 0][ar + h * 64] = v.x;
            As[ac + 1][ar + h * 64] = v.y;
            As[ac + 2][ar + h * 64] = v.z;
            As[ac + 3][ar + h * 64] = v.w;
        }
        #pragma unroll
        for (int i2 = 0; i2 < 2; i2++) {
            int idx = tid + i2 * 256;
            int r = idx >> 5, cc = (idx & 31) * 4;
            *(float4*)&Bs[r][cc] = *(const float4*)(Sv + (size_t)(k0 + r) * 128 + cc);
        }
        __syncthreads();
        #pragma unroll
        for (int kk = 0; kk < 16; kk++) {
            float av[8], bv[8];
            *(float4*)&av[0] = *(const float4*)&As[kk][ty * 8];
            *(float4*)&av[4] = *(const float4*)&As[kk][ty * 8 + 4];
            *(float4*)&bv[0] = *(const float4*)&Bs[kk][tx * 8];
            *(float4*)&bv[4] = *(const float4*)&Bs[kk][tx * 8 + 4];
            #pragma unroll
            for (int i = 0; i < 8; i++)
                #pragma unroll
                for (int j = 0; j < 8; j++) acc[i][j] += av[i] * bv[j];
        }
        __syncthreads();
    }
    #pragma unroll
    for (int i = 0; i < 8; i++) {
        float* erow = g_E + ((size_t)b * DD + d0 + ty * 8 + i) * 128 + tx * 8;
        *(float4*)&erow[0] = *(float4*)&acc[i][0];
        *(float4*)&erow[4] = *(float4*)&acc[i][4];
    }
}

__global__ void __launch_bounds__(256) k_weffT(const float* __restrict__ W) {
    int b = blockIdx.z, o0 = blockIdx.y * 128, d0 = blockIdx.x * 128;
    __shared__ __align__(16) float As[16][132];
    __shared__ __align__(16) float Bs[16][132];
    int tid = threadIdx.x, tx = tid & 15, ty = tid >> 4;
    const float* Eb = g_E + (size_t)b * DD * 128;
    float acc[8][8] = {};
    int ar = tid >> 2, ac = (tid & 3) * 4;
    for (int k0 = 0; k0 < 128; k0 += 16) {
        #pragma unroll
        for (int i2 = 0; i2 < 2; i2++) {
            int idx = tid + i2 * 256;
            int r = idx >> 5, cc = (idx & 31) * 4;
            *(float4*)&As[r][cc] = *(const float4*)(g_T0 + (size_t)(k0 + r) * OUTD + o0 + cc);
        }
        #pragma unroll
        for (int h = 0; h < 2; h++) {
            int d = d0 + ar + h * 64;
            float4 v = *(const float4*)(Eb + (size_t)d * 128 + k0 + ac);
            Bs[ac + 0][ar + h * 64] = v.x;
            Bs[ac + 1][ar + h * 64] = v.y;
            Bs[ac + 2][ar + h * 64] = v.z;
            Bs[ac + 3][ar + h * 64] = v.w;
        }
        __syncthreads();
        #pragma unroll
        for (int kk = 0; kk < 16; kk++) {
            float av[8], bv[8];
            *(float4*)&av[0] = *(const float4*)&As[kk][ty * 8];
            *(float4*)&av[4] = *(const float4*)&As[kk][ty * 8 + 4];
            *(float4*)&bv[0] = *(const float4*)&Bs[kk][tx * 8];
            *(float4*)&bv[4] = *(const float4*)&Bs[kk][tx * 8 + 4];
            #pragma unroll
            for (int i = 0; i < 8; i++)
                #pragma unroll
                for (int j = 0; j < 8; j++) acc[i][j] += av[i] * bv[j];
        }
        __syncthreads();
    }
    float g = g_g2[b];
    #pragma unroll
    for (int i = 0; i < 8; i++) {
        int o = o0 + ty * 8 + i;
        const float* wrow = W + (size_t)o * DD + d0 + tx * 8;
        __align__(16) __half hb[8];
        #pragma unroll
        for (int j = 0; j < 8; j++)
            hb[j] = __float2half(wrow[j] + g * acc[i][j]);
        *(uint4*)(g_WTh + ((size_t)b * OUTD + o) * DD + d0 + tx * 8) = *(uint4*)hb;
    }
}

__global__ void k_lm(const float* __restrict__ x, const float* __restrict__ ker) {
    int by = blockIdx.x;
    int b = by >> 5, y = by & 31, d = threadIdx.x;
    const float* xb = x + (size_t)b * NN * DD + d;
    float lg = g_lg[b];
    if (y == 0) g_lmh[(size_t)b * NN * DD + d] = __float2half(xb[0]);
    float k00 = ker[d * 9 + 0], k01 = ker[d * 9 + 1], k02 = ker[d * 9 + 2];
    float k10 = ker[d * 9 + 3], k11 = ker[d * 9 + 4], k12 = ker[d * 9 + 5];
    float k20 = ker[d * 9 + 6], k21 = ker[d * 9 + 7], k22 = ker[d * 9 + 8];
    bool up = (y > 0), dn = (y < 31);
    float ua = 0.f, ma = 0.f, la = 0.f, ub, mb, mc, lb, uc, lc;
    ub = up ? xb[(size_t)(1 + (y - 1) * 32) * DD] : 0.f;
    mb = xb[(size_t)(1 + y * 32) * DD];
    lb = dn ? xb[(size_t)(1 + (y + 1) * 32) * DD] : 0.f;
    for (int xx = 0; xx < 32; xx++) {
        if (xx < 31) {
            uc = up ? xb[(size_t)(1 + (y - 1) * 32 + xx + 1) * DD] : 0.f;
            mc = xb[(size_t)(1 + y * 32 + xx + 1) * DD];
            lc = dn ? xb[(size_t)(1 + (y + 1) * 32 + xx + 1) * DD] : 0.f;
        } else { uc = mc = lc = 0.f; }
        float conv = ua * k00 + ub * k01 + uc * k02 + ma * k10 + mb * k11 + mc * k12
                   + la * k20 + lb * k21 + lc * k22;
        float v = mb + lg * (conv - mb);
        g_lmh[((size_t)b * NN + 1 + y * 32 + xx) * DD + d] = __float2half(v);
        ua = ub; ub = uc; ma = mb; mb = mc; la = lb; lb = lc;
    }
}

// ---- main GEMM: 256x128 tiles, 512 threads (4x4 warps), single fp16 A x B ----
#define BK 32
#define ROWB 80
#define ATILE (256 * ROWB)       // 20480
#define BTILE (128 * ROWB)       // 10240
#define STAGEB (ATILE + BTILE)   // 30720
#define NCH 12
#define GEMM_SMEM (3 * STAGEB)   // 92160

__device__ __forceinline__ void cp16(uint32_t dst, const void* src) {
    asm volatile("cp.async.cg.shared.global [%0], [%1], 16;" :: "r"(dst), "l"(src) : "memory");
}

__global__ void __launch_bounds__(512, 1) k_gemm_mma(const float* __restrict__ bias,
                                                     float* __restrict__ out) {
    extern __shared__ __align__(16) unsigned char sm[];
    __shared__ float s_bias[128], s_scale[128];
    int b = blockIdx.z, m0 = blockIdx.y * 256, n0 = blockIdx.x * 128;
    int tid = threadIdx.x, lane = tid & 31, wid = tid >> 5;
    int wm = wid & 3, wn = wid >> 2;      // 4 (m) x 4 (n) warps

    if (tid < 128) {
        s_bias[tid] = bias[n0 + tid];
        s_scale[tid] = g_scale[b * OUTD + n0 + tid];
    }

    uint32_t smb = smem_u32(sm);
    float acc[4][4][4];
    #pragma unroll
    for (int i = 0; i < 4; i++)
        #pragma unroll
        for (int j = 0; j < 4; j++)
            #pragma unroll
            for (int q = 0; q < 4; q++) acc[i][j][q] = 0.f;

    int rA = tid >> 2, chA = tid & 3;     // A rows rA, rA+128
    size_t aoff0 = ((size_t)b * NN + m0 + rA) * DD;
    size_t aoff1 = ((size_t)b * NN + m0 + rA + 128) * DD;
    size_t boff  = ((size_t)b * OUTD + n0 + rA) * DD;   // rA<128 only for B

    #define LOAD_CHUNK(c, s) do { \
        int k0 = (c) * BK; \
        uint32_t Ax = smb + (uint32_t)(s) * STAGEB; \
        uint32_t Bh = Ax + ATILE; \
        cp16(Ax + rA * ROWB + chA * 16, g_lmh + aoff0 + k0 + chA * 8); \
        cp16(Ax + (rA + 128) * ROWB + chA * 16, g_lmh + aoff1 + k0 + chA * 8); \
        if (rA < 128) cp16(Bh + rA * ROWB + chA * 16, g_WTh + boff + k0 + chA * 8); \
    } while (0)

    #define LDMA(dst, base, mf) do { \
        uint32_t addr = (base) + (uint32_t)((wm * 64 + (mf) * 16 + (lane & 15)) * ROWB \
                      + (kstep * 2 + (lane >> 4)) * 16); \
        asm volatile("ldmatrix.sync.aligned.m8n8.x4.shared.b16 {%0,%1,%2,%3}, [%4];" \
            : "=r"((dst)[0]), "=r"((dst)[1]), "=r"((dst)[2]), "=r"((dst)[3]) : "r"(addr)); \
    } while (0)

    #define LDMB(dst, base) do { \
        int g = lane >> 3; \
        _Pragma("unroll") \
        for (int nf2 = 0; nf2 < 2; nf2++) { \
            uint32_t addr = (base) + (uint32_t)((wn * 32 + nf2 * 16 + ((g >> 1) << 3) + (lane & 7)) * ROWB \
                          + (kstep * 2 + (g & 1)) * 16); \
            uint32_t q0, q1, q2, q3; \
            asm volatile("ldmatrix.sync.aligned.m8n8.x4.shared.b16 {%0,%1,%2,%3}, [%4];" \
                : "=r"(q0), "=r"(q1), "=r"(q2), "=r"(q3) : "r"(addr)); \
            (dst)[nf2 * 2][0] = q0; (dst)[nf2 * 2][1] = q1; \
            (dst)[nf2 * 2 + 1][0] = q2; (dst)[nf2 * 2 + 1][1] = q3; \
        } \
    } while (0)

    #define MMAS(af, bfr) do { \
        _Pragma("unroll") \
        for (int mf = 0; mf < 4; mf++) \
            _Pragma("unroll") \
            for (int nf = 0; nf < 4; nf++) { \
                asm volatile( \
                    "mma.sync.aligned.m16n8k16.row.col.f32.f16.f16.f32 " \
                    "{%0,%1,%2,%3}, {%4,%5,%6,%7}, {%8,%9}, {%0,%1,%2,%3};" \
                    : "+f"(acc[mf][nf][0]), "+f"(acc[mf][nf][1]), \
                      "+f"(acc[mf][nf][2]), "+f"(acc[mf][nf][3]) \
                    : "r"((af)[mf][0]), "r"((af)[mf][1]), "r"((af)[mf][2]), "r"((af)[mf][3]), \
                      "r"((bfr)[nf][0]), "r"((bfr)[nf][1])); \
            } \
    } while (0)

    LOAD_CHUNK(0, 0);
    asm volatile("cp.async.commit_group;" ::: "memory");
    LOAD_CHUNK(1, 1);
    asm volatile("cp.async.commit_group;" ::: "memory");

    for (int c = 0; c < NCH; c++) {
        if (c + 2 < NCH) {
            LOAD_CHUNK(c + 2, (c + 2) % 3);
            asm volatile("cp.async.commit_group;" ::: "memory");
            asm volatile("cp.async.wait_group 2;" ::: "memory");
        } else if (c + 1 < NCH) {
            asm volatile("cp.async.wait_group 1;" ::: "memory");
        } else {
            asm volatile("cp.async.wait_group 0;" ::: "memory");
        }
        __syncthreads();

        uint32_t Ax = smb + (uint32_t)(c % 3) * STAGEB;
        uint32_t Bh = Ax + ATILE;
        #pragma unroll
        for (int kstep = 0; kstep < 2; kstep++) {
            uint32_t ah[4][4], bh[4][2];
            #pragma unroll
            for (int mf = 0; mf < 4; mf++) LDMA(ah[mf], Ax, mf);
            LDMB(bh, Bh);
            MMAS(ah, bh);
        }
        __syncthreads();
    }

    int gr = lane >> 2, gc = (lane & 3) * 2;
    #pragma unroll
    for (int mf = 0; mf < 4; mf++) {
        #pragma unroll
        for (int nf = 0; nf < 4; nf++) {
            int nl = wn * 32 + nf * 8 + gc;
            float b0 = s_bias[nl], b1 = s_bias[nl + 1];
            float sc0 = s_scale[nl], sc1 = s_scale[nl + 1];
            int mrow = m0 + wm * 64 + mf * 16 + gr;
            float2 v0 = make_float2((acc[mf][nf][0] + b0) * sc0, (acc[mf][nf][1] + b1) * sc1);
            *(float2*)(out + ((size_t)b * NN + mrow) * OUTD + n0 + nl) = v0;
            float2 v1 = make_float2((acc[mf][nf][2] + b0) * sc0, (acc[mf][nf][3] + b1) * sc1);
            *(float2*)(out + ((size_t)b * NN + mrow + 8) * OUTD + n0 + nl) = v1;
        }
    }
}

// last token (row 1024), exact fp32: out = lm.W + g2*(lm.E).T0
__global__ void k_lastrow(const float* __restrict__ W, const float* __restrict__ bias,
                          float* __restrict__ out) {
    int b = blockIdx.x, t = threadIdx.x;
    __shared__ float av[DD];
    __shared__ float zl[128];
    size_t lro = ((size_t)b * NN + 1024) * DD;
    av[t] = __half2float(g_lmh[lro + t]);
    __syncthreads();
    if (t < 128) {
        float a = 0.f;
        const float* Eb = g_E + (size_t)b * DD * 128;
        #pragma unroll 4
        for (int d = 0; d < DD; d++) a += av[d] * Eb[(size_t)d * 128 + t];
        zl[t] = a;
    }
    __syncthreads();
    float acc = 0.f;
    const float* wrow = W + (size_t)t * DD;
    #pragma unroll 4
    for (int d = 0; d < DD; d++) acc += av[d] * wrow[d];
    float c2 = 0.f;
    #pragma unroll 4
    for (int j = 0; j < 128; j++) c2 += zl[j] * g_T0[(size_t)j * OUTD + t];
    out[((size_t)b * NN + 1024) * OUTD + t] = (acc + g_g2[b] * c2 + bias[t]) * g_scale[b * OUTD + t];
}

// ---------------- launch: fork-join streams ----------------
static cudaStream_t s1, s2;
static cudaEvent_t ev_fork, ev_prep, ev_PT0, ev_ctrl, ev_lm;

extern "C" void kernel_launch(void* const* d_in, const int* in_sizes, int n_in,
                              void* d_out, int out_size) {
    const float* x      = (const float*)d_in[0];
    const float* W      = (const float*)d_in[1];
    const float* bias   = (const float*)d_in[2];
    const float* Lb     = (const float*)d_in[3];
    const float* Rb     = (const float*)d_in[4];
    const float* sbasis = (const float*)d_in[5];
    const float* ss     = (const float*)d_in[6];
    const float* dwk    = (const float*)d_in[7];
    const float* w1     = (const float*)d_in[8];
    const float* b1     = (const float*)d_in[9];
    const float* w_rot  = (const float*)d_in[10];
    const float* b_rot  = (const float*)d_in[11];
    const float* w_rg   = (const float*)d_in[12];
    const float* b_rg   = (const float*)d_in[13];
    const float* w_lg   = (const float*)d_in[14];
    const float* b_lg   = (const float*)d_in[15];
    const float* w_sc   = (const float*)d_in[16];
    const float* b_sc   = (const float*)d_in[17];
    float* out = (float*)d_out;

    static int init_done = 0;
    if (!init_done) {
        cudaFuncSetAttribute(k_lusolve, cudaFuncAttributeMaxDynamicSharedMemorySize, LUSOLVE_SMEM);
        cudaFuncSetAttribute(k_gemm_mma, cudaFuncAttributeMaxDynamicSharedMemorySize, GEMM_SMEM);
        cudaStreamCreateWithFlags(&s1, cudaStreamNonBlocking);
        cudaStreamCreateWithFlags(&s2, cudaStreamNonBlocking);
        cudaEventCreateWithFlags(&ev_fork, cudaEventDisableTiming);
        cudaEventCreateWithFlags(&ev_prep, cudaEventDisableTiming);
        cudaEventCreateWithFlags(&ev_PT0, cudaEventDisableTiming);
        cudaEventCreateWithFlags(&ev_ctrl, cudaEventDisableTiming);
        cudaEventCreateWithFlags(&ev_lm, cudaEventDisableTiming);
        init_done = 1;
    }

    cudaEventRecord(ev_fork, 0);
    cudaStreamWaitEvent(s1, ev_fork, 0);

    k_prep<<<200, 256, 0, s1>>>(Lb, Rb);
    cudaEventRecord(ev_prep, s1);
    k_PT0<<<16, 256, 0, s1>>>(W);
    cudaEventRecord(ev_PT0, s1);

    k_stats<<<dim3(BB, NSC), 384>>>(x);
    cudaStreamWaitEvent(0, ev_prep, 0);
    k_ctrl<<<BB, 512>>>(w1, b1, w_rot, b_rot, w_rg, b_rg, w_lg, b_lg, w_sc, b_sc, sbasis, ss);
    cudaEventRecord(ev_ctrl, 0);

    cudaStreamWaitEvent(s2, ev_ctrl, 0);
    k_lm<<<BB * 32, 384, 0, s2>>>(x, dwk);
    cudaEventRecord(ev_lm, s2);

    cudaStreamWaitEvent(0, ev_PT0, 0);
    k_lusolve<<<BB, 128, LUSOLVE_SMEM>>>();
    k_E<<<dim3(1, 3, BB), 256>>>();
    k_weffT<<<dim3(3, 3, BB), 256>>>(W);

    cudaStreamWaitEvent(0, ev_lm, 0);
    k_gemm_mma<<<dim3(3, 4, BB), 512, GEMM_SMEM>>>(bias, out);
    k_lastrow<<<BB, 384>>>(W, bias, out);
}

// round 14
// speedup vs baseline: 1.2127x; 1.2127x over previous
#include <cuda_runtime.h>
#include <cuda_fp16.h>
#include <math.h>
#include <stdint.h>

#define BB 64
#define NN 1025
#define DD 384
#define KKB 8
#define HH 128
#define CIN 1152
#define OUTD 384
#define NSC 8

__device__ float g_cls[BB * DD];
__device__ float g_part[BB * NSC * 2 * DD];
__device__ float g_U[DD * 128];
__device__ float g_V[DD * 128];
__device__ float g_nrm[KKB];
__device__ float g_P[128 * 128];
__device__ float g_T0[128 * OUTD];
__device__ float g_s[BB * KKB];
__device__ float g_g2[BB];
__device__ float g_lg[BB];
__device__ float g_scale[BB * OUTD];
__device__ float g_Sinv[BB * 128 * 128];
__device__ float g_E[BB * DD * 128];
__device__ __half g_WTh[(size_t)BB * OUTD * DD];
__device__ __half g_xh[(size_t)BB * NN * DD];
__device__ __half g_ch[(size_t)BB * NN * DD];
__device__ __half g_lmh[(size_t)BB * NN * DD + 127 * DD];

__device__ __forceinline__ uint32_t smem_u32(const void* p) {
    return (uint32_t)__cvta_generic_to_shared(p);
}

__global__ void __launch_bounds__(384) k_stats(const float* __restrict__ x) {
    int b = blockIdx.x, c = blockIdx.y, d = threadIdx.x;
    const float* xb = x + (size_t)b * NN * DD + d;
    float s = 0.f, s2 = 0.f;
    int n0 = c * 128;
    #pragma unroll 4
    for (int r = 0; r < 128; r++) {
        float v = xb[(size_t)(n0 + r) * DD];
        s += v; s2 += v * v;
    }
    if (c == NSC - 1) {
        float v = xb[(size_t)1024 * DD];
        s += v; s2 += v * v;
    }
    if (c == 0) g_cls[b * DD + d] = xb[0];
    g_part[((b * NSC + c) * 2 + 0) * DD + d] = s;
    g_part[((b * NSC + c) * 2 + 1) * DD + d] = s2;
}

__global__ void k_prep(const float* __restrict__ Lb, const float* __restrict__ Rb) {
    int bid = blockIdx.x;
    if (bid < 192) {
        int idx = bid * 256 + threadIdx.x;
        int d = idx >> 7, j = idx & 127, k = j >> 4, t = j & 15;
        if (t < 8) {
            g_U[d * 128 + j] = Lb[(k * DD + d) * 8 + t];
            g_V[d * 128 + j] = Rb[(k * DD + d) * 8 + t];
        } else {
            g_U[d * 128 + j] = -Rb[(k * DD + d) * 8 + t - 8];
            g_V[d * 128 + j] =  Lb[(k * DD + d) * 8 + t - 8];
        }
    } else {
        int k = bid - 192, t = threadIdx.x;
        int which = t / 64, e = t % 64, i = e / 8, j = e % 8;
        __shared__ float gm[3][8][8];
        __shared__ float red[192];
        if (t < 192) {
            const float* Ap = (which == 0) ? Lb : Rb;
            const float* Bp = (which == 1) ? Rb : Lb;
            float acc = 0.f;
            #pragma unroll 8
            for (int d = 0; d < DD; d++)
                acc += Ap[(k * DD + d) * 8 + i] * Bp[(k * DD + d) * 8 + j];
            gm[which][i][j] = acc;
        }
        __syncthreads();
        float part = 0.f;
        if (t < 64) part = 2.f * (gm[0][i][j] * gm[1][i][j] - gm[2][i][j] * gm[2][j][i]);
        if (t < 192) red[t] = part;
        __syncthreads();
        if (t == 0) {
            float s = 0.f;
            for (int q = 0; q < 64; q++) s += red[q];
            g_nrm[k] = fmaxf(sqrtf(s), 1e-6f);
        }
    }
}

__global__ void __launch_bounds__(256) k_PT0(const float* __restrict__ W) {
    int bid = blockIdx.x;
    int tid = threadIdx.x;
    if (bid < 4) {
        int i0 = (bid >> 1) * 64, j0 = (bid & 1) * 64;
        __shared__ float As[16][68];
        __shared__ float Bs[16][68];
        int tx = tid & 15, ty = tid >> 4;
        int r = tid >> 4, c4 = (tid & 15) * 4;
        float acc[4][4] = {};
        for (int k0 = 0; k0 < DD; k0 += 16) {
            *(float4*)&As[r][c4] = *(const float4*)(g_V + (size_t)(k0 + r) * 128 + i0 + c4);
            *(float4*)&Bs[r][c4] = *(const float4*)(g_U + (size_t)(k0 + r) * 128 + j0 + c4);
            __syncthreads();
            #pragma unroll
            for (int kk = 0; kk < 16; kk++) {
                float av[4], bv[4];
                #pragma unroll
                for (int i = 0; i < 4; i++) av[i] = As[kk][ty * 4 + i];
                #pragma unroll
                for (int j = 0; j < 4; j++) bv[j] = Bs[kk][tx * 4 + j];
                #pragma unroll
                for (int i = 0; i < 4; i++)
                    #pragma unroll
                    for (int j = 0; j < 4; j++) acc[i][j] += av[i] * bv[j];
            }
            __syncthreads();
        }
        #pragma unroll
        for (int i = 0; i < 4; i++)
            *(float4*)(g_P + (size_t)(i0 + ty * 4 + i) * 128 + j0 + tx * 4) = *(float4*)acc[i];
    } else {
        int b2 = bid - 4;
        int o0 = (b2 % 3) * 128, j0 = (b2 / 3) * 32;
        __shared__ float As2[16][36];
        __shared__ float Bs2[16][132];
        int tx = tid & 31, ty = tid >> 5;
        int ro = tid >> 1, co = tid & 1;
        int ja = tid & 31, ka = tid >> 5;
        float acc[4][4] = {};
        for (int k0 = 0; k0 < DD; k0 += 16) {
            As2[ka][ja]     = g_V[(size_t)(k0 + ka) * 128 + j0 + ja];
            As2[ka + 8][ja] = g_V[(size_t)(k0 + ka + 8) * 128 + j0 + ja];
            #pragma unroll
            for (int h = 0; h < 2; h++) {
                float4 w = *(const float4*)(W + (size_t)(o0 + ro) * DD + k0 + co * 8 + h * 4);
                Bs2[co * 8 + h * 4 + 0][ro] = w.x;
                Bs2[co * 8 + h * 4 + 1][ro] = w.y;
                Bs2[co * 8 + h * 4 + 2][ro] = w.z;
                Bs2[co * 8 + h * 4 + 3][ro] = w.w;
            }
            __syncthreads();
            #pragma unroll
            for (int kk = 0; kk < 16; kk++) {
                float av[4], bv[4];
                #pragma unroll
                for (int i = 0; i < 4; i++) av[i] = As2[kk][ty * 4 + i];
                #pragma unroll
                for (int j = 0; j < 4; j++) bv[j] = Bs2[kk][tx * 4 + j];
                #pragma unroll
                for (int i = 0; i < 4; i++)
                    #pragma unroll
                    for (int j = 0; j < 4; j++) acc[i][j] += av[i] * bv[j];
            }
            __syncthreads();
        }
        #pragma unroll
        for (int i = 0; i < 4; i++)
            *(float4*)(g_T0 + (size_t)(j0 + ty * 4 + i) * OUTD + o0 + tx * 4) = *(float4*)acc[i];
    }
}

__global__ void __launch_bounds__(512) k_ctrl(
        const float* __restrict__ w1, const float* __restrict__ b1,
        const float* __restrict__ w_rot, const float* __restrict__ b_rot,
        const float* __restrict__ w_rg, const float* __restrict__ b_rg,
        const float* __restrict__ w_lg, const float* __restrict__ b_lg,
        const float* __restrict__ w_sc, const float* __restrict__ b_sc,
        const float* __restrict__ scale_basis, const float* __restrict__ ss_ptr) {
    int b = blockIdx.x, t = threadIdx.x;
    int lane = t & 31, wid = t >> 5;
    __shared__ float zs[CIN];
    __shared__ float hs[HH];
    __shared__ float coef[KKB];
    const float inv_n = 1.f / (float)NN;
    if (t < DD) {
        float s = 0.f, s2 = 0.f;
        #pragma unroll
        for (int c = 0; c < NSC; c++) {
            s  += g_part[((b * NSC + c) * 2 + 0) * DD + t];
            s2 += g_part[((b * NSC + c) * 2 + 1) * DD + t];
        }
        float mean = s * inv_n;
        zs[t] = g_cls[b * DD + t];
        zs[384 + t] = mean;
        zs[768 + t] = s2 * inv_n - mean * mean;
    }
    __syncthreads();
    for (int to = wid; to < HH; to += 16) {
        const float* w = w1 + (size_t)to * CIN;
        float acc = 0.f;
        for (int c = lane; c < CIN; c += 32) acc += zs[c] * w[c];
        #pragma unroll
        for (int off = 16; off; off >>= 1) acc += __shfl_down_sync(0xFFFFFFFFu, acc, off);
        if (lane == 0) {
            float xg = acc + b1[to];
            float x3 = xg * xg * xg;
            hs[to] = 0.5f * xg * (1.f + tanhf(0.7978845608028654f * (xg + 0.044715f * x3)));
        }
    }
    __syncthreads();
    if (t < 8) {
        float acc = b_rot[t];
        for (int c = 0; c < HH; c++) acc += hs[c] * w_rot[t * HH + c];
        g_s[b * 8 + t] = 0.5f * tanhf(acc) / g_nrm[t];
    } else if (t == 8) {
        float acc = b_rg[0];
        for (int c = 0; c < HH; c++) acc += hs[c] * w_rg[c];
        g_g2[b] = 2.f / (1.f + expf(-acc));
    } else if (t == 9) {
        float acc = b_lg[0];
        for (int c = 0; c < HH; c++) acc += hs[c] * w_lg[c];
        g_lg[b] = 1.f / (1.f + expf(-acc));
    } else if (t >= 16 && t < 24) {
        int k = t - 16;
        float acc = b_sc[k];
        for (int c = 0; c < HH; c++) acc += hs[c] * w_sc[k * HH + c];
        coef[k] = tanhf(acc);
    }
    __syncthreads();
    float ss = ss_ptr[0];
    if (t < OUTD) {
        float acc = 0.f;
        for (int k = 0; k < KKB; k++) acc += coef[k] * scale_basis[k * OUTD + t];
        g_scale[b * OUTD + t] = 1.f + ss * tanhf(acc);
    }
}

#define LUP 129
#define LUSOLVE_SMEM (2 * 128 * LUP * 4)
__global__ void __launch_bounds__(128) k_lusolve() {
    extern __shared__ float smf[];
    float* a = smf;
    float* y = smf + 128 * LUP;
    __shared__ float sb[8];
    int b = blockIdx.x, i = threadIdx.x;
    if (i < 8) sb[i] = g_s[b * 8 + i];
    __syncthreads();
    for (int q = 0; q < 128; q++)
        a[i * LUP + q] = (i == q ? 1.f : 0.f) - g_P[i * 128 + q] * sb[q >> 4];
    for (int p = 0; p < 127; p++) {
        __syncthreads();
        if (i > p) {
            float l = a[i * LUP + p] / a[p * LUP + p];
            a[i * LUP + p] = l;
            for (int q = p + 1; q < 128; q++) a[i * LUP + q] -= l * a[p * LUP + q];
        }
    }
    __syncthreads();
    for (int p = 0; p < 128; p++) {
        float a0 = 0.f, a1 = 0.f, a2 = 0.f, a3 = 0.f;
        const float* row = a + p * LUP;
        int q = 0;
        for (; q + 3 < p; q += 4) {
            a0 += row[q] * y[q * LUP + i];
            a1 += row[q + 1] * y[(q + 1) * LUP + i];
            a2 += row[q + 2] * y[(q + 2) * LUP + i];
            a3 += row[q + 3] * y[(q + 3) * LUP + i];
        }
        for (; q < p; q++) a0 += row[q] * y[q * LUP + i];
        y[p * LUP + i] = ((p == i) ? 1.f : 0.f) - (a0 + a1) - (a2 + a3);
    }
    for (int p = 127; p >= 0; p--) {
        float a0 = 0.f, a1 = 0.f, a2 = 0.f, a3 = 0.f;
        const float* row = a + p * LUP;
        int q = p + 1;
        for (; q + 3 < 128; q += 4) {
            a0 += row[q] * y[q * LUP + i];
            a1 += row[q + 1] * y[(q + 1) * LUP + i];
            a2 += row[q + 2] * y[(q + 2) * LUP + i];
            a3 += row[q + 3] * y[(q + 3) * LUP + i];
        }
        for (; q < 128; q++) a0 += row[q] * y[q * LUP + i];
        y[p * LUP + i] = (y[p * LUP + i] - (a0 + a1) - (a2 + a3)) / row[p];
    }
    float* sv = g_Sinv + (size_t)b * 128 * 128;
    for (int p = 0; p < 128; p++)
        sv[p * 128 + i] = sb[p >> 4] * y[p * LUP + i];
}

__global__ void __launch_bounds__(256) k_E() {
    int b = blockIdx.z, d0 = blockIdx.y * 128;
    __shared__ __align__(16) float As[16][132];
    __shared__ __align__(16) float Bs[16][132];
    int tid = threadIdx.x, tx = tid & 15, ty = tid >> 4;
    const float* Sv = g_Sinv + (size_t)b * 128 * 128;
    float acc[8][8] = {};
    int ar = tid >> 2, ac = (tid & 3) * 4;
    for (int k0 = 0; k0 < 128; k0 += 16) {
        #pragma unroll
        for (int h = 0; h < 2; h++) {
            int d = d0 + ar + h * 64;
            float4 v = *(const float4*)(g_U + (size_t)d * 128 + k0 + ac);
            As[ac + 0][ar + h * 64] = v.x;
            As[ac + 1][ar + h * 64] = v.y;
            As[ac + 2][ar + h * 64] = v.z;
            As[ac + 3][ar + h * 64] = v.w;
        }
        #pragma unroll
        for (int i2 = 0; i2 < 2; i2++) {
            int idx = tid + i2 * 256;
            int r = idx >> 5, cc = (idx & 31) * 4;
            *(float4*)&Bs[r][cc] = *(const float4*)(Sv + (size_t)(k0 + r) * 128 + cc);
        }
        __syncthreads();
        #pragma unroll
        for (int kk = 0; kk < 16; kk++) {
            float av[8], bv[8];
            *(float4*)&av[0] = *(const float4*)&As[kk][ty * 8];
            *(float4*)&av[4] = *(const float4*)&As[kk][ty * 8 + 4];
            *(float4*)&bv[0] = *(const float4*)&Bs[kk][tx * 8];
            *(float4*)&bv[4] = *(const float4*)&Bs[kk][tx * 8 + 4];
            #pragma unroll
            for (int i = 0; i < 8; i++)
                #pragma unroll
                for (int j = 0; j < 8; j++) acc[i][j] += av[i] * bv[j];
        }
        __syncthreads();
    }
    #pragma unroll
    for (int i = 0; i < 8; i++) {
        float* erow = g_E + ((size_t)b * DD + d0 + ty * 8 + i) * 128 + tx * 8;
        *(float4*)&erow[0] = *(float4*)&acc[i][0];
        *(float4*)&erow[4] = *(float4*)&acc[i][4];
    }
}

__global__ void __launch_bounds__(256) k_weffT(const float* __restrict__ W) {
    int b = blockIdx.z, o0 = blockIdx.y * 128, d0 = blockIdx.x * 128;
    __shared__ __align__(16) float As[16][132];
    __shared__ __align__(16) float Bs[16][132];
    int tid = threadIdx.x, tx = tid & 15, ty = tid >> 4;
    const float* Eb = g_E + (size_t)b * DD * 128;
    float acc[8][8] = {};
    int ar = tid >> 2, ac = (tid & 3) * 4;
    for (int k0 = 0; k0 < 128; k0 += 16) {
        #pragma unroll
        for (int i2 = 0; i2 < 2; i2++) {
            int idx = tid + i2 * 256;
            int r = idx >> 5, cc = (idx & 31) * 4;
            *(float4*)&As[r][cc] = *(const float4*)(g_T0 + (size_t)(k0 + r) * OUTD + o0 + cc);
        }
        #pragma unroll
        for (int h = 0; h < 2; h++) {
            int d = d0 + ar + h * 64;
            float4 v = *(const float4*)(Eb + (size_t)d * 128 + k0 + ac);
            Bs[ac + 0][ar + h * 64] = v.x;
            Bs[ac + 1][ar + h * 64] = v.y;
            Bs[ac + 2][ar + h * 64] = v.z;
            Bs[ac + 3][ar + h * 64] = v.w;
        }
        __syncthreads();
        #pragma unroll
        for (int kk = 0; kk < 16; kk++) {
            float av[8], bv[8];
            *(float4*)&av[0] = *(const float4*)&As[kk][ty * 8];
            *(float4*)&av[4] = *(const float4*)&As[kk][ty * 8 + 4];
            *(float4*)&bv[0] = *(const float4*)&Bs[kk][tx * 8];
            *(float4*)&bv[4] = *(const float4*)&Bs[kk][tx * 8 + 4];
            #pragma unroll
            for (int i = 0; i < 8; i++)
                #pragma unroll
                for (int j = 0; j < 8; j++) acc[i][j] += av[i] * bv[j];
        }
        __syncthreads();
    }
    float g = g_g2[b];
    #pragma unroll
    for (int i = 0; i < 8; i++) {
        int o = o0 + ty * 8 + i;
        const float* wrow = W + (size_t)o * DD + d0 + tx * 8;
        __align__(16) __half hb[8];
        #pragma unroll
        for (int j = 0; j < 8; j++)
            hb[j] = __float2half(wrow[j] + g * acc[i][j]);
        *(uint4*)(g_WTh + ((size_t)b * OUTD + o) * DD + d0 + tx * 8) = *(uint4*)hb;
    }
}

// conv precompute: xh = fp16(x), ch = fp16(conv - x). NO dependencies.
__global__ void k_conv(const float* __restrict__ x, const float* __restrict__ ker) {
    int by = blockIdx.x;
    int b = by >> 5, y = by & 31, d = threadIdx.x;
    const float* xb = x + (size_t)b * NN * DD + d;
    if (y == 0) {
        g_xh[(size_t)b * NN * DD + d] = __float2half(xb[0]);
        g_ch[(size_t)b * NN * DD + d] = __float2half(0.f);
    }
    float k00 = ker[d * 9 + 0], k01 = ker[d * 9 + 1], k02 = ker[d * 9 + 2];
    float k10 = ker[d * 9 + 3], k11 = ker[d * 9 + 4], k12 = ker[d * 9 + 5];
    float k20 = ker[d * 9 + 6], k21 = ker[d * 9 + 7], k22 = ker[d * 9 + 8];
    bool up = (y > 0), dn = (y < 31);
    float ua = 0.f, ma = 0.f, la = 0.f, ub, mb, mc, lb, uc, lc;
    ub = up ? xb[(size_t)(1 + (y - 1) * 32) * DD] : 0.f;
    mb = xb[(size_t)(1 + y * 32) * DD];
    lb = dn ? xb[(size_t)(1 + (y + 1) * 32) * DD] : 0.f;
    for (int xx = 0; xx < 32; xx++) {
        if (xx < 31) {
            uc = up ? xb[(size_t)(1 + (y - 1) * 32 + xx + 1) * DD] : 0.f;
            mc = xb[(size_t)(1 + y * 32 + xx + 1) * DD];
            lc = dn ? xb[(size_t)(1 + (y + 1) * 32 + xx + 1) * DD] : 0.f;
        } else { uc = mc = lc = 0.f; }
        float conv = ua * k00 + ub * k01 + uc * k02 + ma * k10 + mb * k11 + mc * k12
                   + la * k20 + lb * k21 + lc * k22;
        size_t oi = ((size_t)b * NN + 1 + y * 32 + xx) * DD + d;
        g_xh[oi] = __float2half(mb);
        g_ch[oi] = __float2half(conv - mb);
        ua = ub; ub = uc; ma = mb; mb = mc; la = lb; lb = lc;
    }
}

// combine: lmh = xh + lg * ch (streaming half2, after ctrl)
#define CMB_ELEMS ((size_t)BB * NN * DD)
#define CMB_VEC (CMB_ELEMS / 8)        // 3,148,800 uint4-of-half groups
__global__ void __launch_bounds__(256) k_combine() {
    size_t idx = (size_t)blockIdx.x * 256 + threadIdx.x;
    if (idx >= CMB_VEC) return;
    int b = (int)(idx / ((size_t)NN * DD / 8));
    __half2 lg2 = __float2half2_rn(g_lg[b]);
    uint4 xv = *(const uint4*)(g_xh + idx * 8);
    uint4 cv = *(const uint4*)(g_ch + idx * 8);
    uint4 ov;
    __half2* xp = (__half2*)&xv;
    __half2* cp = (__half2*)&cv;
    __half2* op = (__half2*)&ov;
    #pragma unroll
    for (int q = 0; q < 4; q++) op[q] = __hfma2(lg2, cp[q], xp[q]);
    *(uint4*)(g_lmh + idx * 8) = ov;
}

// ---- main GEMM (R11 config): 128x128 tiles, 256 thr, 3-stage, grid y=9 ----
#define BK 32
#define ROWB 80
#define TILEB (128 * ROWB)
#define STAGEB (2 * TILEB)
#define NCH 12
#define GEMM_SMEM (3 * STAGEB)

__device__ __forceinline__ void cp16(uint32_t dst, const void* src) {
    asm volatile("cp.async.cg.shared.global [%0], [%1], 16;" :: "r"(dst), "l"(src) : "memory");
}

__global__ void __launch_bounds__(256, 2) k_gemm_mma(const float* __restrict__ bias,
                                                     float* __restrict__ out) {
    extern __shared__ __align__(16) unsigned char sm[];
    __shared__ float s_bias[128], s_scale[128];
    int b = blockIdx.z, m0 = blockIdx.y * 128, n0 = blockIdx.x * 128;
    int tid = threadIdx.x, lane = tid & 31, wid = tid >> 5;
    int wm = wid & 1, wn = wid >> 1;

    if (tid < 128) {
        s_bias[tid] = bias[n0 + tid];
        s_scale[tid] = g_scale[b * OUTD + n0 + tid];
    }

    uint32_t smb = smem_u32(sm);
    float acc[4][4][4];
    #pragma unroll
    for (int i = 0; i < 4; i++)
        #pragma unroll
        for (int j = 0; j < 4; j++)
            #pragma unroll
            for (int q = 0; q < 4; q++) acc[i][j][q] = 0.f;

    int ci0 = tid, ci1 = tid + 256;
    int r0 = ci0 >> 2, ch0 = ci0 & 3;
    int r1 = ci1 >> 2, ch1 = ci1 & 3;
    int am0 = m0 + r0; if (am0 > NN - 1) am0 = NN - 1;
    int am1 = m0 + r1; if (am1 > NN - 1) am1 = NN - 1;
    size_t aoff0 = ((size_t)b * NN + am0) * DD;
    size_t aoff1 = ((size_t)b * NN + am1) * DD;
    size_t boff0 = ((size_t)b * OUTD + n0 + r0) * DD;
    size_t boff1 = ((size_t)b * OUTD + n0 + r1) * DD;

    #define LOAD_CHUNK(c, s) do { \
        int k0 = (c) * BK; \
        uint32_t Ax = smb + (uint32_t)(s) * STAGEB; \
        uint32_t Bh = Ax + TILEB; \
        cp16(Ax + r0 * ROWB + ch0 * 16, g_lmh + aoff0 + k0 + ch0 * 8); \
        cp16(Ax + r1 * ROWB + ch1 * 16, g_lmh + aoff1 + k0 + ch1 * 8); \
        cp16(Bh + r0 * ROWB + ch0 * 16, g_WTh + boff0 + k0 + ch0 * 8); \
        cp16(Bh + r1 * ROWB + ch1 * 16, g_WTh + boff1 + k0 + ch1 * 8); \
    } while (0)

    #define LDMA(dst, base, mf) do { \
        uint32_t addr = (base) + (uint32_t)((wm * 64 + (mf) * 16 + (lane & 15)) * ROWB \
                      + (kstep * 2 + (lane >> 4)) * 16); \
        asm volatile("ldmatrix.sync.aligned.m8n8.x4.shared.b16 {%0,%1,%2,%3}, [%4];" \
            : "=r"((dst)[0]), "=r"((dst)[1]), "=r"((dst)[2]), "=r"((dst)[3]) : "r"(addr)); \
    } while (0)

    #define LDMB(dst, base) do { \
        int g = lane >> 3; \
        _Pragma("unroll") \
        for (int nf2 = 0; nf2 < 2; nf2++) { \
            uint32_t addr = (base) + (uint32_t)((wn * 32 + nf2 * 16 + ((g >> 1) << 3) + (lane & 7)) * ROWB \
                          + (kstep * 2 + (g & 1)) * 16); \
            uint32_t q0, q1, q2, q3; \
            asm volatile("ldmatrix.sync.aligned.m8n8.x4.shared.b16 {%0,%1,%2,%3}, [%4];" \
                : "=r"(q0), "=r"(q1), "=r"(q2), "=r"(q3) : "r"(addr)); \
            (dst)[nf2 * 2][0] = q0; (dst)[nf2 * 2][1] = q1; \
            (dst)[nf2 * 2 + 1][0] = q2; (dst)[nf2 * 2 + 1][1] = q3; \
        } \
    } while (0)

    #define MMAS(af, bfr) do { \
        _Pragma("unroll") \
        for (int mf = 0; mf < 4; mf++) \
            _Pragma("unroll") \
            for (int nf = 0; nf < 4; nf++) { \
                asm volatile( \
                    "mma.sync.aligned.m16n8k16.row.col.f32.f16.f16.f32 " \
                    "{%0,%1,%2,%3}, {%4,%5,%6,%7}, {%8,%9}, {%0,%1,%2,%3};" \
                    : "+f"(acc[mf][nf][0]), "+f"(acc[mf][nf][1]), \
                      "+f"(acc[mf][nf][2]), "+f"(acc[mf][nf][3]) \
                    : "r"((af)[mf][0]), "r"((af)[mf][1]), "r"((af)[mf][2]), "r"((af)[mf][3]), \
                      "r"((bfr)[nf][0]), "r"((bfr)[nf][1])); \
            } \
    } while (0)

    LOAD_CHUNK(0, 0);
    asm volatile("cp.async.commit_group;" ::: "memory");
    LOAD_CHUNK(1, 1);
    asm volatile("cp.async.commit_group;" ::: "memory");

    for (int c = 0; c < NCH; c++) {
        if (c + 2 < NCH) {
            LOAD_CHUNK(c + 2, (c + 2) % 3);
            asm volatile("cp.async.commit_group;" ::: "memory");
            asm volatile("cp.async.wait_group 2;" ::: "memory");
        } else if (c + 1 < NCH) {
            asm volatile("cp.async.wait_group 1;" ::: "memory");
        } else {
            asm volatile("cp.async.wait_group 0;" ::: "memory");
        }
        __syncthreads();

        uint32_t Ax = smb + (uint32_t)(c % 3) * STAGEB;
        uint32_t Bh = Ax + TILEB;
        #pragma unroll
        for (int kstep = 0; kstep < 2; kstep++) {
            uint32_t ah[4][4], bh[4][2];
            #pragma unroll
            for (int mf = 0; mf < 4; mf++) LDMA(ah[mf], Ax, mf);
            LDMB(bh, Bh);
            MMAS(ah, bh);
        }
        __syncthreads();
    }

    int gr = lane >> 2, gc = (lane & 3) * 2;
    #pragma unroll
    for (int mf = 0; mf < 4; mf++) {
        #pragma unroll
        for (int nf = 0; nf < 4; nf++) {
            int nl = wn * 32 + nf * 8 + gc;
            float b0 = s_bias[nl], b1 = s_bias[nl + 1];
            float sc0 = s_scale[nl], sc1 = s_scale[nl + 1];
            int mrow = m0 + wm * 64 + mf * 16 + gr;
            if (mrow < NN) {
                float2 v0 = make_float2((acc[mf][nf][0] + b0) * sc0, (acc[mf][nf][1] + b1) * sc1);
                *(float2*)(out + ((size_t)b * NN + mrow) * OUTD + n0 + nl) = v0;
            }
            if (mrow + 8 < NN) {
                float2 v1 = make_float2((acc[mf][nf][2] + b0) * sc0, (acc[mf][nf][3] + b1) * sc1);
                *(float2*)(out + ((size_t)b * NN + mrow + 8) * OUTD + n0 + nl) = v1;
            }
        }
    }
}

// ---------------- launch: fork-join streams ----------------
static cudaStream_t s1, s2;
static cudaEvent_t ev_fork, ev_prep, ev_PT0, ev_ctrl, ev_lm;

extern "C" void kernel_launch(void* const* d_in, const int* in_sizes, int n_in,
                              void* d_out, int out_size) {
    const float* x      = (const float*)d_in[0];
    const float* W      = (const float*)d_in[1];
    const float* bias   = (const float*)d_in[2];
    const float* Lb     = (const float*)d_in[3];
    const float* Rb     = (const float*)d_in[4];
    const float* sbasis = (const float*)d_in[5];
    const float* ss     = (const float*)d_in[6];
    const float* dwk    = (const float*)d_in[7];
    const float* w1     = (const float*)d_in[8];
    const float* b1     = (const float*)d_in[9];
    const float* w_rot  = (const float*)d_in[10];
    const float* b_rot  = (const float*)d_in[11];
    const float* w_rg   = (const float*)d_in[12];
    const float* b_rg   = (const float*)d_in[13];
    const float* w_lg   = (const float*)d_in[14];
    const float* b_lg   = (const float*)d_in[15];
    const float* w_sc   = (const float*)d_in[16];
    const float* b_sc   = (const float*)d_in[17];
    float* out = (float*)d_out;

    static int init_done = 0;
    if (!init_done) {
        cudaFuncSetAttribute(k_lusolve, cudaFuncAttributeMaxDynamicSharedMemorySize, LUSOLVE_SMEM);
        cudaFuncSetAttribute(k_gemm_mma, cudaFuncAttributeMaxDynamicSharedMemorySize, GEMM_SMEM);
        cudaStreamCreateWithFlags(&s1, cudaStreamNonBlocking);
        cudaStreamCreateWithFlags(&s2, cudaStreamNonBlocking);
        cudaEventCreateWithFlags(&ev_fork, cudaEventDisableTiming);
        cudaEventCreateWithFlags(&ev_prep, cudaEventDisableTiming);
        cudaEventCreateWithFlags(&ev_PT0, cudaEventDisableTiming);
        cudaEventCreateWithFlags(&ev_ctrl, cudaEventDisableTiming);
        cudaEventCreateWithFlags(&ev_lm, cudaEventDisableTiming);
        init_done = 1;
    }

    cudaEventRecord(ev_fork, 0);
    cudaStreamWaitEvent(s1, ev_fork, 0);
    cudaStreamWaitEvent(s2, ev_fork, 0);

    // s2: conv precompute — no deps, starts at t=0
    k_conv<<<BB * 32, 384, 0, s2>>>(x, dwk);

    // s1: basis chain
    k_prep<<<200, 256, 0, s1>>>(Lb, Rb);
    cudaEventRecord(ev_prep, s1);
    k_PT0<<<16, 256, 0, s1>>>(W);
    cudaEventRecord(ev_PT0, s1);

    // origin: stats -> ctrl
    k_stats<<<dim3(BB, NSC), 384>>>(x);
    cudaStreamWaitEvent(0, ev_prep, 0);
    k_ctrl<<<BB, 512>>>(w1, b1, w_rot, b_rot, w_rg, b_rg, w_lg, b_lg, w_sc, b_sc, sbasis, ss);
    cudaEventRecord(ev_ctrl, 0);

    // s2: combine (needs conv on same stream + ctrl)
    cudaStreamWaitEvent(s2, ev_ctrl, 0);
    k_combine<<<(int)((CMB_VEC + 255) / 256), 256, 0, s2>>>();
    cudaEventRecord(ev_lm, s2);

    // origin: solve chain
    cudaStreamWaitEvent(0, ev_PT0, 0);
    k_lusolve<<<BB, 128, LUSOLVE_SMEM>>>();
    k_E<<<dim3(1, 3, BB), 256>>>();
    k_weffT<<<dim3(3, 3, BB), 256>>>(W);

    // join combine, then main GEMM (grid y=9 covers row 1024)
    cudaStreamWaitEvent(0, ev_lm, 0);
    k_gemm_mma<<<dim3(3, 9, BB), 256, GEMM_SMEM>>>(bias, out);
}

// round 15
// speedup vs baseline: 1.2132x; 1.0004x over previous
#include <cuda_runtime.h>
#include <cuda_fp16.h>
#include <math.h>
#include <stdint.h>

#define BB 64
#define NN 1025
#define DD 384
#define KKB 8
#define HH 128
#define CIN 1152
#define OUTD 384
#define NSC 8

__device__ float g_cls[BB * DD];
__device__ float g_part[BB * NSC * 2 * DD];
__device__ float g_U[DD * 128];
__device__ float g_V[DD * 128];
__device__ float g_nrm[KKB];
__device__ float g_P[128 * 128];
__device__ float g_T0[128 * OUTD];
__device__ float g_s[BB * KKB];
__device__ float g_g2[BB];
__device__ float g_lg[BB];
__device__ float g_scale[BB * OUTD];
__device__ float g_Sinv[BB * 128 * 128];
__device__ float g_E[BB * DD * 128];
__device__ __half g_WTh[(size_t)BB * OUTD * DD];
__device__ __half g_lmh[(size_t)BB * NN * DD + 127 * DD];

__device__ __forceinline__ uint32_t smem_u32(const void* p) {
    return (uint32_t)__cvta_generic_to_shared(p);
}

__global__ void __launch_bounds__(384) k_stats(const float* __restrict__ x) {
    int b = blockIdx.x, c = blockIdx.y, d = threadIdx.x;
    const float* xb = x + (size_t)b * NN * DD + d;
    float s = 0.f, s2 = 0.f;
    int n0 = c * 128;
    #pragma unroll 4
    for (int r = 0; r < 128; r++) {
        float v = xb[(size_t)(n0 + r) * DD];
        s += v; s2 += v * v;
    }
    if (c == NSC - 1) {
        float v = xb[(size_t)1024 * DD];
        s += v; s2 += v * v;
    }
    if (c == 0) g_cls[b * DD + d] = xb[0];
    g_part[((b * NSC + c) * 2 + 0) * DD + d] = s;
    g_part[((b * NSC + c) * 2 + 1) * DD + d] = s2;
}

__global__ void k_prep(const float* __restrict__ Lb, const float* __restrict__ Rb) {
    int bid = blockIdx.x;
    if (bid < 192) {
        int idx = bid * 256 + threadIdx.x;
        int d = idx >> 7, j = idx & 127, k = j >> 4, t = j & 15;
        if (t < 8) {
            g_U[d * 128 + j] = Lb[(k * DD + d) * 8 + t];
            g_V[d * 128 + j] = Rb[(k * DD + d) * 8 + t];
        } else {
            g_U[d * 128 + j] = -Rb[(k * DD + d) * 8 + t - 8];
            g_V[d * 128 + j] =  Lb[(k * DD + d) * 8 + t - 8];
        }
    } else {
        int k = bid - 192, t = threadIdx.x;
        int which = t / 64, e = t % 64, i = e / 8, j = e % 8;
        __shared__ float gm[3][8][8];
        __shared__ float red[192];
        if (t < 192) {
            const float* Ap = (which == 0) ? Lb : Rb;
            const float* Bp = (which == 1) ? Rb : Lb;
            float acc = 0.f;
            #pragma unroll 8
            for (int d = 0; d < DD; d++)
                acc += Ap[(k * DD + d) * 8 + i] * Bp[(k * DD + d) * 8 + j];
            gm[which][i][j] = acc;
        }
        __syncthreads();
        float part = 0.f;
        if (t < 64) part = 2.f * (gm[0][i][j] * gm[1][i][j] - gm[2][i][j] * gm[2][j][i]);
        if (t < 192) red[t] = part;
        __syncthreads();
        if (t == 0) {
            float s = 0.f;
            for (int q = 0; q < 64; q++) s += red[q];
            g_nrm[k] = fmaxf(sqrtf(s), 1e-6f);
        }
    }
}

__global__ void __launch_bounds__(256) k_PT0(const float* __restrict__ W) {
    int bid = blockIdx.x;
    int tid = threadIdx.x;
    if (bid < 4) {
        int i0 = (bid >> 1) * 64, j0 = (bid & 1) * 64;
        __shared__ float As[16][68];
        __shared__ float Bs[16][68];
        int tx = tid & 15, ty = tid >> 4;
        int r = tid >> 4, c4 = (tid & 15) * 4;
        float acc[4][4] = {};
        for (int k0 = 0; k0 < DD; k0 += 16) {
            *(float4*)&As[r][c4] = *(const float4*)(g_V + (size_t)(k0 + r) * 128 + i0 + c4);
            *(float4*)&Bs[r][c4] = *(const float4*)(g_U + (size_t)(k0 + r) * 128 + j0 + c4);
            __syncthreads();
            #pragma unroll
            for (int kk = 0; kk < 16; kk++) {
                float av[4], bv[4];
                #pragma unroll
                for (int i = 0; i < 4; i++) av[i] = As[kk][ty * 4 + i];
                #pragma unroll
                for (int j = 0; j < 4; j++) bv[j] = Bs[kk][tx * 4 + j];
                #pragma unroll
                for (int i = 0; i < 4; i++)
                    #pragma unroll
                    for (int j = 0; j < 4; j++) acc[i][j] += av[i] * bv[j];
            }
            __syncthreads();
        }
        #pragma unroll
        for (int i = 0; i < 4; i++)
            *(float4*)(g_P + (size_t)(i0 + ty * 4 + i) * 128 + j0 + tx * 4) = *(float4*)acc[i];
    } else {
        int b2 = bid - 4;
        int o0 = (b2 % 3) * 128, j0 = (b2 / 3) * 32;
        __shared__ float As2[16][36];
        __shared__ float Bs2[16][132];
        int tx = tid & 31, ty = tid >> 5;
        int ro = tid >> 1, co = tid & 1;
        int ja = tid & 31, ka = tid >> 5;
        float acc[4][4] = {};
        for (int k0 = 0; k0 < DD; k0 += 16) {
            As2[ka][ja]     = g_V[(size_t)(k0 + ka) * 128 + j0 + ja];
            As2[ka + 8][ja] = g_V[(size_t)(k0 + ka + 8) * 128 + j0 + ja];
            #pragma unroll
            for (int h = 0; h < 2; h++) {
                float4 w = *(const float4*)(W + (size_t)(o0 + ro) * DD + k0 + co * 8 + h * 4);
                Bs2[co * 8 + h * 4 + 0][ro] = w.x;
                Bs2[co * 8 + h * 4 + 1][ro] = w.y;
                Bs2[co * 8 + h * 4 + 2][ro] = w.z;
                Bs2[co * 8 + h * 4 + 3][ro] = w.w;
            }
            __syncthreads();
            #pragma unroll
            for (int kk = 0; kk < 16; kk++) {
                float av[4], bv[4];
                #pragma unroll
                for (int i = 0; i < 4; i++) av[i] = As2[kk][ty * 4 + i];
                #pragma unroll
                for (int j = 0; j < 4; j++) bv[j] = Bs2[kk][tx * 4 + j];
                #pragma unroll
                for (int i = 0; i < 4; i++)
                    #pragma unroll
                    for (int j = 0; j < 4; j++) acc[i][j] += av[i] * bv[j];
            }
            __syncthreads();
        }
        #pragma unroll
        for (int i = 0; i < 4; i++)
            *(float4*)(g_T0 + (size_t)(j0 + ty * 4 + i) * OUTD + o0 + tx * 4) = *(float4*)acc[i];
    }
}

__global__ void __launch_bounds__(512) k_ctrl(
        const float* __restrict__ w1, const float* __restrict__ b1,
        const float* __restrict__ w_rot, const float* __restrict__ b_rot,
        const float* __restrict__ w_rg, const float* __restrict__ b_rg,
        const float* __restrict__ w_lg, const float* __restrict__ b_lg,
        const float* __restrict__ w_sc, const float* __restrict__ b_sc,
        const float* __restrict__ scale_basis, const float* __restrict__ ss_ptr) {
    int b = blockIdx.x, t = threadIdx.x;
    int lane = t & 31, wid = t >> 5;
    __shared__ float zs[CIN];
    __shared__ float hs[HH];
    __shared__ float coef[KKB];
    const float inv_n = 1.f / (float)NN;
    if (t < DD) {
        float s = 0.f, s2 = 0.f;
        #pragma unroll
        for (int c = 0; c < NSC; c++) {
            s  += g_part[((b * NSC + c) * 2 + 0) * DD + t];
            s2 += g_part[((b * NSC + c) * 2 + 1) * DD + t];
        }
        float mean = s * inv_n;
        zs[t] = g_cls[b * DD + t];
        zs[384 + t] = mean;
        zs[768 + t] = s2 * inv_n - mean * mean;
    }
    __syncthreads();
    for (int to = wid; to < HH; to += 16) {
        const float* w = w1 + (size_t)to * CIN;
        float acc = 0.f;
        for (int c = lane; c < CIN; c += 32) acc += zs[c] * w[c];
        #pragma unroll
        for (int off = 16; off; off >>= 1) acc += __shfl_down_sync(0xFFFFFFFFu, acc, off);
        if (lane == 0) {
            float xg = acc + b1[to];
            float x3 = xg * xg * xg;
            hs[to] = 0.5f * xg * (1.f + tanhf(0.7978845608028654f * (xg + 0.044715f * x3)));
        }
    }
    __syncthreads();
    if (t < 8) {
        float acc = b_rot[t];
        for (int c = 0; c < HH; c++) acc += hs[c] * w_rot[t * HH + c];
        g_s[b * 8 + t] = 0.5f * tanhf(acc) / g_nrm[t];
    } else if (t == 8) {
        float acc = b_rg[0];
        for (int c = 0; c < HH; c++) acc += hs[c] * w_rg[c];
        g_g2[b] = 2.f / (1.f + expf(-acc));
    } else if (t == 9) {
        float acc = b_lg[0];
        for (int c = 0; c < HH; c++) acc += hs[c] * w_lg[c];
        g_lg[b] = 1.f / (1.f + expf(-acc));
    } else if (t >= 16 && t < 24) {
        int k = t - 16;
        float acc = b_sc[k];
        for (int c = 0; c < HH; c++) acc += hs[c] * w_sc[k * HH + c];
        coef[k] = tanhf(acc);
    }
    __syncthreads();
    float ss = ss_ptr[0];
    if (t < OUTD) {
        float acc = 0.f;
        for (int k = 0; k < KKB; k++) acc += coef[k] * scale_basis[k * OUTD + t];
        g_scale[b * OUTD + t] = 1.f + ss * tanhf(acc);
    }
}

#define LUP 129
#define LUSOLVE_SMEM (2 * 128 * LUP * 4)
__global__ void __launch_bounds__(128) k_lusolve() {
    extern __shared__ float smf[];
    float* a = smf;
    float* y = smf + 128 * LUP;
    __shared__ float sb[8];
    int b = blockIdx.x, i = threadIdx.x;
    if (i < 8) sb[i] = g_s[b * 8 + i];
    __syncthreads();
    for (int q = 0; q < 128; q++)
        a[i * LUP + q] = (i == q ? 1.f : 0.f) - g_P[i * 128 + q] * sb[q >> 4];
    for (int p = 0; p < 127; p++) {
        __syncthreads();
        if (i > p) {
            float l = a[i * LUP + p] / a[p * LUP + p];
            a[i * LUP + p] = l;
            for (int q = p + 1; q < 128; q++) a[i * LUP + q] -= l * a[p * LUP + q];
        }
    }
    __syncthreads();
    for (int p = 0; p < 128; p++) {
        float a0 = 0.f, a1 = 0.f, a2 = 0.f, a3 = 0.f;
        const float* row = a + p * LUP;
        int q = 0;
        for (; q + 3 < p; q += 4) {
            a0 += row[q] * y[q * LUP + i];
            a1 += row[q + 1] * y[(q + 1) * LUP + i];
            a2 += row[q + 2] * y[(q + 2) * LUP + i];
            a3 += row[q + 3] * y[(q + 3) * LUP + i];
        }
        for (; q < p; q++) a0 += row[q] * y[q * LUP + i];
        y[p * LUP + i] = ((p == i) ? 1.f : 0.f) - (a0 + a1) - (a2 + a3);
    }
    for (int p = 127; p >= 0; p--) {
        float a0 = 0.f, a1 = 0.f, a2 = 0.f, a3 = 0.f;
        const float* row = a + p * LUP;
        int q = p + 1;
        for (; q + 3 < 128; q += 4) {
            a0 += row[q] * y[q * LUP + i];
            a1 += row[q + 1] * y[(q + 1) * LUP + i];
            a2 += row[q + 2] * y[(q + 2) * LUP + i];
            a3 += row[q + 3] * y[(q + 3) * LUP + i];
        }
        for (; q < 128; q++) a0 += row[q] * y[q * LUP + i];
        y[p * LUP + i] = (y[p * LUP + i] - (a0 + a1) - (a2 + a3)) / row[p];
    }
    float* sv = g_Sinv + (size_t)b * 128 * 128;
    for (int p = 0; p < 128; p++)
        sv[p * 128 + i] = sb[p >> 4] * y[p * LUP + i];
}

__global__ void __launch_bounds__(256) k_E() {
    int b = blockIdx.z, d0 = blockIdx.y * 128;
    __shared__ __align__(16) float As[16][132];
    __shared__ __align__(16) float Bs[16][132];
    int tid = threadIdx.x, tx = tid & 15, ty = tid >> 4;
    const float* Sv = g_Sinv + (size_t)b * 128 * 128;
    float acc[8][8] = {};
    int ar = tid >> 2, ac = (tid & 3) * 4;
    for (int k0 = 0; k0 < 128; k0 += 16) {
        #pragma unroll
        for (int h = 0; h < 2; h++) {
            int d = d0 + ar + h * 64;
            float4 v = *(const float4*)(g_U + (size_t)d * 128 + k0 + ac);
            As[ac + 0][ar + h * 64] = v.x;
            As[ac + 1][ar + h * 64] = v.y;
            As[ac + 2][ar + h * 64] = v.z;
            As[ac + 3][ar + h * 64] = v.w;
        }
        #pragma unroll
        for (int i2 = 0; i2 < 2; i2++) {
            int idx = tid + i2 * 256;
            int r = idx >> 5, cc = (idx & 31) * 4;
            *(float4*)&Bs[r][cc] = *(const float4*)(Sv + (size_t)(k0 + r) * 128 + cc);
        }
        __syncthreads();
        #pragma unroll
        for (int kk = 0; kk < 16; kk++) {
            float av[8], bv[8];
            *(float4*)&av[0] = *(const float4*)&As[kk][ty * 8];
            *(float4*)&av[4] = *(const float4*)&As[kk][ty * 8 + 4];
            *(float4*)&bv[0] = *(const float4*)&Bs[kk][tx * 8];
            *(float4*)&bv[4] = *(const float4*)&Bs[kk][tx * 8 + 4];
            #pragma unroll
            for (int i = 0; i < 8; i++)
                #pragma unroll
                for (int j = 0; j < 8; j++) acc[i][j] += av[i] * bv[j];
        }
        __syncthreads();
    }
    #pragma unroll
    for (int i = 0; i < 8; i++) {
        float* erow = g_E + ((size_t)b * DD + d0 + ty * 8 + i) * 128 + tx * 8;
        *(float4*)&erow[0] = *(float4*)&acc[i][0];
        *(float4*)&erow[4] = *(float4*)&acc[i][4];
    }
}

__global__ void __launch_bounds__(256) k_weffT(const float* __restrict__ W) {
    int b = blockIdx.z, o0 = blockIdx.y * 128, d0 = blockIdx.x * 128;
    __shared__ __align__(16) float As[16][132];
    __shared__ __align__(16) float Bs[16][132];
    int tid = threadIdx.x, tx = tid & 15, ty = tid >> 4;
    const float* Eb = g_E + (size_t)b * DD * 128;
    float acc[8][8] = {};
    int ar = tid >> 2, ac = (tid & 3) * 4;
    for (int k0 = 0; k0 < 128; k0 += 16) {
        #pragma unroll
        for (int i2 = 0; i2 < 2; i2++) {
            int idx = tid + i2 * 256;
            int r = idx >> 5, cc = (idx & 31) * 4;
            *(float4*)&As[r][cc] = *(const float4*)(g_T0 + (size_t)(k0 + r) * OUTD + o0 + cc);
        }
        #pragma unroll
        for (int h = 0; h < 2; h++) {
            int d = d0 + ar + h * 64;
            float4 v = *(const float4*)(Eb + (size_t)d * 128 + k0 + ac);
            Bs[ac + 0][ar + h * 64] = v.x;
            Bs[ac + 1][ar + h * 64] = v.y;
            Bs[ac + 2][ar + h * 64] = v.z;
            Bs[ac + 3][ar + h * 64] = v.w;
        }
        __syncthreads();
        #pragma unroll
        for (int kk = 0; kk < 16; kk++) {
            float av[8], bv[8];
            *(float4*)&av[0] = *(const float4*)&As[kk][ty * 8];
            *(float4*)&av[4] = *(const float4*)&As[kk][ty * 8 + 4];
            *(float4*)&bv[0] = *(const float4*)&Bs[kk][tx * 8];
            *(float4*)&bv[4] = *(const float4*)&Bs[kk][tx * 8 + 4];
            #pragma unroll
            for (int i = 0; i < 8; i++)
                #pragma unroll
                for (int j = 0; j < 8; j++) acc[i][j] += av[i] * bv[j];
        }
        __syncthreads();
    }
    float g = g_g2[b];
    #pragma unroll
    for (int i = 0; i < 8; i++) {
        int o = o0 + ty * 8 + i;
        const float* wrow = W + (size_t)o * DD + d0 + tx * 8;
        __align__(16) __half hb[8];
        #pragma unroll
        for (int j = 0; j < 8; j++)
            hb[j] = __float2half(wrow[j] + g * acc[i][j]);
        *(uint4*)(g_WTh + ((size_t)b * OUTD + o) * DD + d0 + tx * 8) = *(uint4*)hb;
    }
}

__global__ void k_lm(const float* __restrict__ x, const float* __restrict__ ker) {
    int by = blockIdx.x;
    int b = by >> 5, y = by & 31, d = threadIdx.x;
    const float* xb = x + (size_t)b * NN * DD + d;
    float lg = g_lg[b];
    if (y == 0) g_lmh[(size_t)b * NN * DD + d] = __float2half(xb[0]);
    float k00 = ker[d * 9 + 0], k01 = ker[d * 9 + 1], k02 = ker[d * 9 + 2];
    float k10 = ker[d * 9 + 3], k11 = ker[d * 9 + 4], k12 = ker[d * 9 + 5];
    float k20 = ker[d * 9 + 6], k21 = ker[d * 9 + 7], k22 = ker[d * 9 + 8];
    bool up = (y > 0), dn = (y < 31);
    float ua = 0.f, ma = 0.f, la = 0.f, ub, mb, mc, lb, uc, lc;
    ub = up ? xb[(size_t)(1 + (y - 1) * 32) * DD] : 0.f;
    mb = xb[(size_t)(1 + y * 32) * DD];
    lb = dn ? xb[(size_t)(1 + (y + 1) * 32) * DD] : 0.f;
    for (int xx = 0; xx < 32; xx++) {
        if (xx < 31) {
            uc = up ? xb[(size_t)(1 + (y - 1) * 32 + xx + 1) * DD] : 0.f;
            mc = xb[(size_t)(1 + y * 32 + xx + 1) * DD];
            lc = dn ? xb[(size_t)(1 + (y + 1) * 32 + xx + 1) * DD] : 0.f;
        } else { uc = mc = lc = 0.f; }
        float conv = ua * k00 + ub * k01 + uc * k02 + ma * k10 + mb * k11 + mc * k12
                   + la * k20 + lb * k21 + lc * k22;
        float v = mb + lg * (conv - mb);
        g_lmh[((size_t)b * NN + 1 + y * 32 + xx) * DD + d] = __float2half(v);
        ua = ub; ub = uc; ma = mb; mb = mc; la = lb; lb = lc;
    }
}

// ---- main GEMM: 128x128 tiles, 256 thr, 4-stage pipeline, grid y=9 ----
#define BK 32
#define ROWB 80
#define TILEB (128 * ROWB)
#define STAGEB (2 * TILEB)
#define NCH 12
#define GEMM_SMEM (4 * STAGEB)   // 81920 B

__device__ __forceinline__ void cp16(uint32_t dst, const void* src) {
    asm volatile("cp.async.cg.shared.global [%0], [%1], 16;" :: "r"(dst), "l"(src) : "memory");
}

__global__ void __launch_bounds__(256, 2) k_gemm_mma(const float* __restrict__ bias,
                                                     float* __restrict__ out) {
    extern __shared__ __align__(16) unsigned char sm[];
    __shared__ float s_bias[128], s_scale[128];
    int b = blockIdx.z, m0 = blockIdx.y * 128, n0 = blockIdx.x * 128;
    int tid = threadIdx.x, lane = tid & 31, wid = tid >> 5;
    int wm = wid & 1, wn = wid >> 1;

    if (tid < 128) {
        s_bias[tid] = bias[n0 + tid];
        s_scale[tid] = g_scale[b * OUTD + n0 + tid];
    }

    uint32_t smb = smem_u32(sm);
    float acc[4][4][4];
    #pragma unroll
    for (int i = 0; i < 4; i++)
        #pragma unroll
        for (int j = 0; j < 4; j++)
            #pragma unroll
            for (int q = 0; q < 4; q++) acc[i][j][q] = 0.f;

    int ci0 = tid, ci1 = tid + 256;
    int r0 = ci0 >> 2, ch0 = ci0 & 3;
    int r1 = ci1 >> 2, ch1 = ci1 & 3;
    int am0 = m0 + r0; if (am0 > NN - 1) am0 = NN - 1;
    int am1 = m0 + r1; if (am1 > NN - 1) am1 = NN - 1;
    size_t aoff0 = ((size_t)b * NN + am0) * DD;
    size_t aoff1 = ((size_t)b * NN + am1) * DD;
    size_t boff0 = ((size_t)b * OUTD + n0 + r0) * DD;
    size_t boff1 = ((size_t)b * OUTD + n0 + r1) * DD;

    #define LOAD_CHUNK(c, s) do { \
        int k0 = (c) * BK; \
        uint32_t Ax = smb + (uint32_t)(s) * STAGEB; \
        uint32_t Bh = Ax + TILEB; \
        cp16(Ax + r0 * ROWB + ch0 * 16, g_lmh + aoff0 + k0 + ch0 * 8); \
        cp16(Ax + r1 * ROWB + ch1 * 16, g_lmh + aoff1 + k0 + ch1 * 8); \
        cp16(Bh + r0 * ROWB + ch0 * 16, g_WTh + boff0 + k0 + ch0 * 8); \
        cp16(Bh + r1 * ROWB + ch1 * 16, g_WTh + boff1 + k0 + ch1 * 8); \
    } while (0)

    #define LDMA(dst, base, mf) do { \
        uint32_t addr = (base) + (uint32_t)((wm * 64 + (mf) * 16 + (lane & 15)) * ROWB \
                      + (kstep * 2 + (lane >> 4)) * 16); \
        asm volatile("ldmatrix.sync.aligned.m8n8.x4.shared.b16 {%0,%1,%2,%3}, [%4];" \
            : "=r"((dst)[0]), "=r"((dst)[1]), "=r"((dst)[2]), "=r"((dst)[3]) : "r"(addr)); \
    } while (0)

    #define LDMB(dst, base) do { \
        int g = lane >> 3; \
        _Pragma("unroll") \
        for (int nf2 = 0; nf2 < 2; nf2++) { \
            uint32_t addr = (base) + (uint32_t)((wn * 32 + nf2 * 16 + ((g >> 1) << 3) + (lane & 7)) * ROWB \
                          + (kstep * 2 + (g & 1)) * 16); \
            uint32_t q0, q1, q2, q3; \
            asm volatile("ldmatrix.sync.aligned.m8n8.x4.shared.b16 {%0,%1,%2,%3}, [%4];" \
                : "=r"(q0), "=r"(q1), "=r"(q2), "=r"(q3) : "r"(addr)); \
            (dst)[nf2 * 2][0] = q0; (dst)[nf2 * 2][1] = q1; \
            (dst)[nf2 * 2 + 1][0] = q2; (dst)[nf2 * 2 + 1][1] = q3; \
        } \
    } while (0)

    #define MMAS(af, bfr) do { \
        _Pragma("unroll") \
        for (int mf = 0; mf < 4; mf++) \
            _Pragma("unroll") \
            for (int nf = 0; nf < 4; nf++) { \
                asm volatile( \
                    "mma.sync.aligned.m16n8k16.row.col.f32.f16.f16.f32 " \
                    "{%0,%1,%2,%3}, {%4,%5,%6,%7}, {%8,%9}, {%0,%1,%2,%3};" \
                    : "+f"(acc[mf][nf][0]), "+f"(acc[mf][nf][1]), \
                      "+f"(acc[mf][nf][2]), "+f"(acc[mf][nf][3]) \
                    : "r"((af)[mf][0]), "r"((af)[mf][1]), "r"((af)[mf][2]), "r"((af)[mf][3]), \
                      "r"((bfr)[nf][0]), "r"((bfr)[nf][1])); \
            } \
    } while (0)

    LOAD_CHUNK(0, 0);
    asm volatile("cp.async.commit_group;" ::: "memory");
    LOAD_CHUNK(1, 1);
    asm volatile("cp.async.commit_group;" ::: "memory");
    LOAD_CHUNK(2, 2);
    asm volatile("cp.async.commit_group;" ::: "memory");

    for (int c = 0; c < NCH; c++) {
        if (c + 3 < NCH) {
            LOAD_CHUNK(c + 3, (c + 3) & 3);
            asm volatile("cp.async.commit_group;" ::: "memory");
            asm volatile("cp.async.wait_group 3;" ::: "memory");
        } else if (c + 2 < NCH) {
            asm volatile("cp.async.wait_group 2;" ::: "memory");
        } else if (c + 1 < NCH) {
            asm volatile("cp.async.wait_group 1;" ::: "memory");
        } else {
            asm volatile("cp.async.wait_group 0;" ::: "memory");
        }
        __syncthreads();

        uint32_t Ax = smb + (uint32_t)(c & 3) * STAGEB;
        uint32_t Bh = Ax + TILEB;
        #pragma unroll
        for (int kstep = 0; kstep < 2; kstep++) {
            uint32_t ah[4][4], bh[4][2];
            #pragma unroll
            for (int mf = 0; mf < 4; mf++) LDMA(ah[mf], Ax, mf);
            LDMB(bh, Bh);
            MMAS(ah, bh);
        }
        __syncthreads();
    }

    int gr = lane >> 2, gc = (lane & 3) * 2;
    #pragma unroll
    for (int mf = 0; mf < 4; mf++) {
        #pragma unroll
        for (int nf = 0; nf < 4; nf++) {
            int nl = wn * 32 + nf * 8 + gc;
            float b0 = s_bias[nl], b1 = s_bias[nl + 1];
            float sc0 = s_scale[nl], sc1 = s_scale[nl + 1];
            int mrow = m0 + wm * 64 + mf * 16 + gr;
            if (mrow < NN) {
                float2 v0 = make_float2((acc[mf][nf][0] + b0) * sc0, (acc[mf][nf][1] + b1) * sc1);
                *(float2*)(out + ((size_t)b * NN + mrow) * OUTD + n0 + nl) = v0;
            }
            if (mrow + 8 < NN) {
                float2 v1 = make_float2((acc[mf][nf][2] + b0) * sc0, (acc[mf][nf][3] + b1) * sc1);
                *(float2*)(out + ((size_t)b * NN + mrow + 8) * OUTD + n0 + nl) = v1;
            }
        }
    }
}

// ---------------- launch: fork-join, NO work on legacy stream 0 ----------------
static cudaStream_t s0, s1, s2;
static cudaEvent_t ev_fork, ev_prep, ev_PT0, ev_ctrl, ev_lm, ev_done;

extern "C" void kernel_launch(void* const* d_in, const int* in_sizes, int n_in,
                              void* d_out, int out_size) {
    const float* x      = (const float*)d_in[0];
    const float* W      = (const float*)d_in[1];
    const float* bias   = (const float*)d_in[2];
    const float* Lb     = (const float*)d_in[3];
    const float* Rb     = (const float*)d_in[4];
    const float* sbasis = (const float*)d_in[5];
    const float* ss     = (const float*)d_in[6];
    const float* dwk    = (const float*)d_in[7];
    const float* w1     = (const float*)d_in[8];
    const float* b1     = (const float*)d_in[9];
    const float* w_rot  = (const float*)d_in[10];
    const float* b_rot  = (const float*)d_in[11];
    const float* w_rg   = (const float*)d_in[12];
    const float* b_rg   = (const float*)d_in[13];
    const float* w_lg   = (const float*)d_in[14];
    const float* b_lg   = (const float*)d_in[15];
    const float* w_sc   = (const float*)d_in[16];
    const float* b_sc   = (const float*)d_in[17];
    float* out = (float*)d_out;

    static int init_done = 0;
    if (!init_done) {
        cudaFuncSetAttribute(k_lusolve, cudaFuncAttributeMaxDynamicSharedMemorySize, LUSOLVE_SMEM);
        cudaFuncSetAttribute(k_gemm_mma, cudaFuncAttributeMaxDynamicSharedMemorySize, GEMM_SMEM);
        cudaStreamCreateWithFlags(&s0, cudaStreamNonBlocking);
        cudaStreamCreateWithFlags(&s1, cudaStreamNonBlocking);
        cudaStreamCreateWithFlags(&s2, cudaStreamNonBlocking);
        cudaEventCreateWithFlags(&ev_fork, cudaEventDisableTiming);
        cudaEventCreateWithFlags(&ev_prep, cudaEventDisableTiming);
        cudaEventCreateWithFlags(&ev_PT0, cudaEventDisableTiming);
        cudaEventCreateWithFlags(&ev_ctrl, cudaEventDisableTiming);
        cudaEventCreateWithFlags(&ev_lm, cudaEventDisableTiming);
        cudaEventCreateWithFlags(&ev_done, cudaEventDisableTiming);
        init_done = 1;
    }

    // fork: all three worker streams branch off the capture-origin stream
    cudaEventRecord(ev_fork, 0);
    cudaStreamWaitEvent(s0, ev_fork, 0);
    cudaStreamWaitEvent(s1, ev_fork, 0);
    cudaStreamWaitEvent(s2, ev_fork, 0);

    // s1: basis chain
    k_prep<<<200, 256, 0, s1>>>(Lb, Rb);
    cudaEventRecord(ev_prep, s1);
    k_PT0<<<16, 256, 0, s1>>>(W);
    cudaEventRecord(ev_PT0, s1);

    // s0: stats -> ctrl
    k_stats<<<dim3(BB, NSC), 384, 0, s0>>>(x);
    cudaStreamWaitEvent(s0, ev_prep, 0);
    k_ctrl<<<BB, 512, 0, s0>>>(w1, b1, w_rot, b_rot, w_rg, b_rg, w_lg, b_lg, w_sc, b_sc, sbasis, ss);
    cudaEventRecord(ev_ctrl, s0);

    // s2: lm (needs ctrl)
    cudaStreamWaitEvent(s2, ev_ctrl, 0);
    k_lm<<<BB * 32, 384, 0, s2>>>(x, dwk);
    cudaEventRecord(ev_lm, s2);

    // s0: solve chain (needs P+T0)
    cudaStreamWaitEvent(s0, ev_PT0, 0);
    k_lusolve<<<BB, 128, LUSOLVE_SMEM, s0>>>();
    k_E<<<dim3(1, 3, BB), 256, 0, s0>>>();
    k_weffT<<<dim3(3, 3, BB), 256, 0, s0>>>(W);

    // s0: join lm, main GEMM (grid y=9 covers row 1024)
    cudaStreamWaitEvent(s0, ev_lm, 0);
    k_gemm_mma<<<dim3(3, 9, BB), 256, GEMM_SMEM, s0>>>(bias, out);

    // join back to the origin stream so the harness sees completion
    cudaEventRecord(ev_done, s0);
    cudaStreamWaitEvent(0, ev_done, 0);
}

// round 16
// speedup vs baseline: 1.2590x; 1.0377x over previous
#include <cuda_runtime.h>
#include <cuda_fp16.h>
#include <math.h>
#include <stdint.h>

#define BB 64
#define NN 1025
#define DD 384
#define KKB 8
#define HH 128
#define CIN 1152
#define OUTD 384
#define NSC 8

__device__ float g_cls[BB * DD];
__device__ float g_part[BB * NSC * 2 * DD];
__device__ float g_U[DD * 128];
__device__ float g_V[DD * 128];
__device__ float g_nrm[KKB];
__device__ float g_P[128 * 128];
__device__ float g_T0[128 * OUTD];
__device__ float g_s[BB * KKB];
__device__ float g_g2[BB];
__device__ float g_lg[BB];
__device__ float g_scale[BB * OUTD];
__device__ float g_Sinv[BB * 128 * 128];
__device__ float g_E[BB * DD * 128];
__device__ __half g_WTh[(size_t)BB * OUTD * DD];
__device__ __half g_lmh[(size_t)BB * NN * DD + 127 * DD];

__device__ __forceinline__ uint32_t smem_u32(const void* p) {
    return (uint32_t)__cvta_generic_to_shared(p);
}

__global__ void __launch_bounds__(384) k_stats(const float* __restrict__ x) {
    int b = blockIdx.x, c = blockIdx.y, d = threadIdx.x;
    const float* xb = x + (size_t)b * NN * DD + d;
    float s = 0.f, s2 = 0.f;
    int n0 = c * 128;
    #pragma unroll 4
    for (int r = 0; r < 128; r++) {
        float v = xb[(size_t)(n0 + r) * DD];
        s += v; s2 += v * v;
    }
    if (c == NSC - 1) {
        float v = xb[(size_t)1024 * DD];
        s += v; s2 += v * v;
    }
    if (c == 0) g_cls[b * DD + d] = xb[0];
    g_part[((b * NSC + c) * 2 + 0) * DD + d] = s;
    g_part[((b * NSC + c) * 2 + 1) * DD + d] = s2;
}

__global__ void k_prep(const float* __restrict__ Lb, const float* __restrict__ Rb) {
    int bid = blockIdx.x;
    if (bid < 192) {
        int idx = bid * 256 + threadIdx.x;
        int d = idx >> 7, j = idx & 127, k = j >> 4, t = j & 15;
        if (t < 8) {
            g_U[d * 128 + j] = Lb[(k * DD + d) * 8 + t];
            g_V[d * 128 + j] = Rb[(k * DD + d) * 8 + t];
        } else {
            g_U[d * 128 + j] = -Rb[(k * DD + d) * 8 + t - 8];
            g_V[d * 128 + j] =  Lb[(k * DD + d) * 8 + t - 8];
        }
    } else {
        int k = bid - 192, t = threadIdx.x;
        int which = t / 64, e = t % 64, i = e / 8, j = e % 8;
        __shared__ float gm[3][8][8];
        __shared__ float red[192];
        if (t < 192) {
            const float* Ap = (which == 0) ? Lb : Rb;
            const float* Bp = (which == 1) ? Rb : Lb;
            float acc = 0.f;
            #pragma unroll 8
            for (int d = 0; d < DD; d++)
                acc += Ap[(k * DD + d) * 8 + i] * Bp[(k * DD + d) * 8 + j];
            gm[which][i][j] = acc;
        }
        __syncthreads();
        float part = 0.f;
        if (t < 64) part = 2.f * (gm[0][i][j] * gm[1][i][j] - gm[2][i][j] * gm[2][j][i]);
        if (t < 192) red[t] = part;
        __syncthreads();
        if (t == 0) {
            float s = 0.f;
            for (int q = 0; q < 64; q++) s += red[q];
            g_nrm[k] = fmaxf(sqrtf(s), 1e-6f);
        }
    }
}

__global__ void __launch_bounds__(256) k_PT0(const float* __restrict__ W) {
    int bid = blockIdx.x;
    int tid = threadIdx.x;
    if (bid < 4) {
        int i0 = (bid >> 1) * 64, j0 = (bid & 1) * 64;
        __shared__ float As[16][68];
        __shared__ float Bs[16][68];
        int tx = tid & 15, ty = tid >> 4;
        int r = tid >> 4, c4 = (tid & 15) * 4;
        float acc[4][4] = {};
        for (int k0 = 0; k0 < DD; k0 += 16) {
            *(float4*)&As[r][c4] = *(const float4*)(g_V + (size_t)(k0 + r) * 128 + i0 + c4);
            *(float4*)&Bs[r][c4] = *(const float4*)(g_U + (size_t)(k0 + r) * 128 + j0 + c4);
            __syncthreads();
            #pragma unroll
            for (int kk = 0; kk < 16; kk++) {
                float av[4], bv[4];
                #pragma unroll
                for (int i = 0; i < 4; i++) av[i] = As[kk][ty * 4 + i];
                #pragma unroll
                for (int j = 0; j < 4; j++) bv[j] = Bs[kk][tx * 4 + j];
                #pragma unroll
                for (int i = 0; i < 4; i++)
                    #pragma unroll
                    for (int j = 0; j < 4; j++) acc[i][j] += av[i] * bv[j];
            }
            __syncthreads();
        }
        #pragma unroll
        for (int i = 0; i < 4; i++)
            *(float4*)(g_P + (size_t)(i0 + ty * 4 + i) * 128 + j0 + tx * 4) = *(float4*)acc[i];
    } else {
        int b2 = bid - 4;
        int o0 = (b2 % 3) * 128, j0 = (b2 / 3) * 32;
        __shared__ float As2[16][36];
        __shared__ float Bs2[16][132];
        int tx = tid & 31, ty = tid >> 5;
        int ro = tid >> 1, co = tid & 1;
        int ja = tid & 31, ka = tid >> 5;
        float acc[4][4] = {};
        for (int k0 = 0; k0 < DD; k0 += 16) {
            As2[ka][ja]     = g_V[(size_t)(k0 + ka) * 128 + j0 + ja];
            As2[ka + 8][ja] = g_V[(size_t)(k0 + ka + 8) * 128 + j0 + ja];
            #pragma unroll
            for (int h = 0; h < 2; h++) {
                float4 w = *(const float4*)(W + (size_t)(o0 + ro) * DD + k0 + co * 8 + h * 4);
                Bs2[co * 8 + h * 4 + 0][ro] = w.x;
                Bs2[co * 8 + h * 4 + 1][ro] = w.y;
                Bs2[co * 8 + h * 4 + 2][ro] = w.z;
                Bs2[co * 8 + h * 4 + 3][ro] = w.w;
            }
            __syncthreads();
            #pragma unroll
            for (int kk = 0; kk < 16; kk++) {
                float av[4], bv[4];
                #pragma unroll
                for (int i = 0; i < 4; i++) av[i] = As2[kk][ty * 4 + i];
                #pragma unroll
                for (int j = 0; j < 4; j++) bv[j] = Bs2[kk][tx * 4 + j];
                #pragma unroll
                for (int i = 0; i < 4; i++)
                    #pragma unroll
                    for (int j = 0; j < 4; j++) acc[i][j] += av[i] * bv[j];
            }
            __syncthreads();
        }
        #pragma unroll
        for (int i = 0; i < 4; i++)
            *(float4*)(g_T0 + (size_t)(j0 + ty * 4 + i) * OUTD + o0 + tx * 4) = *(float4*)acc[i];
    }
}

__global__ void __launch_bounds__(512) k_ctrl(
        const float* __restrict__ w1, const float* __restrict__ b1,
        const float* __restrict__ w_rot, const float* __restrict__ b_rot,
        const float* __restrict__ w_rg, const float* __restrict__ b_rg,
        const float* __restrict__ w_lg, const float* __restrict__ b_lg,
        const float* __restrict__ w_sc, const float* __restrict__ b_sc,
        const float* __restrict__ scale_basis, const float* __restrict__ ss_ptr) {
    int b = blockIdx.x, t = threadIdx.x;
    int lane = t & 31, wid = t >> 5;
    __shared__ float zs[CIN];
    __shared__ float hs[HH];
    __shared__ float coef[KKB];
    const float inv_n = 1.f / (float)NN;
    if (t < DD) {
        float s = 0.f, s2 = 0.f;
        #pragma unroll
        for (int c = 0; c < NSC; c++) {
            s  += g_part[((b * NSC + c) * 2 + 0) * DD + t];
            s2 += g_part[((b * NSC + c) * 2 + 1) * DD + t];
        }
        float mean = s * inv_n;
        zs[t] = g_cls[b * DD + t];
        zs[384 + t] = mean;
        zs[768 + t] = s2 * inv_n - mean * mean;
    }
    __syncthreads();
    for (int to = wid; to < HH; to += 16) {
        const float* w = w1 + (size_t)to * CIN;
        float acc = 0.f;
        for (int c = lane; c < CIN; c += 32) acc += zs[c] * w[c];
        #pragma unroll
        for (int off = 16; off; off >>= 1) acc += __shfl_down_sync(0xFFFFFFFFu, acc, off);
        if (lane == 0) {
            float xg = acc + b1[to];
            float x3 = xg * xg * xg;
            hs[to] = 0.5f * xg * (1.f + tanhf(0.7978845608028654f * (xg + 0.044715f * x3)));
        }
    }
    __syncthreads();
    if (t < 8) {
        float acc = b_rot[t];
        for (int c = 0; c < HH; c++) acc += hs[c] * w_rot[t * HH + c];
        g_s[b * 8 + t] = 0.5f * tanhf(acc) / g_nrm[t];
    } else if (t == 8) {
        float acc = b_rg[0];
        for (int c = 0; c < HH; c++) acc += hs[c] * w_rg[c];
        g_g2[b] = 2.f / (1.f + expf(-acc));
    } else if (t == 9) {
        float acc = b_lg[0];
        for (int c = 0; c < HH; c++) acc += hs[c] * w_lg[c];
        g_lg[b] = 1.f / (1.f + expf(-acc));
    } else if (t >= 16 && t < 24) {
        int k = t - 16;
        float acc = b_sc[k];
        for (int c = 0; c < HH; c++) acc += hs[c] * w_sc[k * HH + c];
        coef[k] = tanhf(acc);
    }
    __syncthreads();
    float ss = ss_ptr[0];
    if (t < OUTD) {
        float acc = 0.f;
        for (int k = 0; k < KKB; k++) acc += coef[k] * scale_basis[k * OUTD + t];
        g_scale[b * OUTD + t] = 1.f + ss * tanhf(acc);
    }
}

#define LUP 129
#define LUSOLVE_SMEM (2 * 128 * LUP * 4)
__global__ void __launch_bounds__(128) k_lusolve() {
    extern __shared__ float smf[];
    float* a = smf;
    float* y = smf + 128 * LUP;
    __shared__ float sb[8];
    int b = blockIdx.x, i = threadIdx.x;
    if (i < 8) sb[i] = g_s[b * 8 + i];
    __syncthreads();
    for (int q = 0; q < 128; q++)
        a[i * LUP + q] = (i == q ? 1.f : 0.f) - g_P[i * 128 + q] * sb[q >> 4];
    for (int p = 0; p < 127; p++) {
        __syncthreads();
        if (i > p) {
            float l = a[i * LUP + p] / a[p * LUP + p];
            a[i * LUP + p] = l;
            for (int q = p + 1; q < 128; q++) a[i * LUP + q] -= l * a[p * LUP + q];
        }
    }
    __syncthreads();
    for (int p = 0; p < 128; p++) {
        float a0 = 0.f, a1 = 0.f, a2 = 0.f, a3 = 0.f;
        const float* row = a + p * LUP;
        int q = 0;
        for (; q + 3 < p; q += 4) {
            a0 += row[q] * y[q * LUP + i];
            a1 += row[q + 1] * y[(q + 1) * LUP + i];
            a2 += row[q + 2] * y[(q + 2) * LUP + i];
            a3 += row[q + 3] * y[(q + 3) * LUP + i];
        }
        for (; q < p; q++) a0 += row[q] * y[q * LUP + i];
        y[p * LUP + i] = ((p == i) ? 1.f : 0.f) - (a0 + a1) - (a2 + a3);
    }
    for (int p = 127; p >= 0; p--) {
        float a0 = 0.f, a1 = 0.f, a2 = 0.f, a3 = 0.f;
        const float* row = a + p * LUP;
        int q = p + 1;
        for (; q + 3 < 128; q += 4) {
            a0 += row[q] * y[q * LUP + i];
            a1 += row[q + 1] * y[(q + 1) * LUP + i];
            a2 += row[q + 2] * y[(q + 2) * LUP + i];
            a3 += row[q + 3] * y[(q + 3) * LUP + i];
        }
        for (; q < 128; q++) a0 += row[q] * y[q * LUP + i];
        y[p * LUP + i] = (y[p * LUP + i] - (a0 + a1) - (a2 + a3)) / row[p];
    }
    float* sv = g_Sinv + (size_t)b * 128 * 128;
    for (int p = 0; p < 128; p++)
        sv[p * 128 + i] = sb[p >> 4] * y[p * LUP + i];
}

__global__ void __launch_bounds__(256) k_E() {
    int b = blockIdx.z, d0 = blockIdx.y * 128;
    __shared__ __align__(16) float As[16][132];
    __shared__ __align__(16) float Bs[16][132];
    int tid = threadIdx.x, tx = tid & 15, ty = tid >> 4;
    const float* Sv = g_Sinv + (size_t)b * 128 * 128;
    float acc[8][8] = {};
    int ar = tid >> 2, ac = (tid & 3) * 4;
    for (int k0 = 0; k0 < 128; k0 += 16) {
        #pragma unroll
        for (int h = 0; h < 2; h++) {
            int d = d0 + ar + h * 64;
            float4 v = *(const float4*)(g_U + (size_t)d * 128 + k0 + ac);
            As[ac + 0][ar + h * 64] = v.x;
            As[ac + 1][ar + h * 64] = v.y;
            As[ac + 2][ar + h * 64] = v.z;
            As[ac + 3][ar + h * 64] = v.w;
        }
        #pragma unroll
        for (int i2 = 0; i2 < 2; i2++) {
            int idx = tid + i2 * 256;
            int r = idx >> 5, cc = (idx & 31) * 4;
            *(float4*)&Bs[r][cc] = *(const float4*)(Sv + (size_t)(k0 + r) * 128 + cc);
        }
        __syncthreads();
        #pragma unroll
        for (int kk = 0; kk < 16; kk++) {
            float av[8], bv[8];
            *(float4*)&av[0] = *(const float4*)&As[kk][ty * 8];
            *(float4*)&av[4] = *(const float4*)&As[kk][ty * 8 + 4];
            *(float4*)&bv[0] = *(const float4*)&Bs[kk][tx * 8];
            *(float4*)&bv[4] = *(const float4*)&Bs[kk][tx * 8 + 4];
            #pragma unroll
            for (int i = 0; i < 8; i++)
                #pragma unroll
                for (int j = 0; j < 8; j++) acc[i][j] += av[i] * bv[j];
        }
        __syncthreads();
    }
    #pragma unroll
    for (int i = 0; i < 8; i++) {
        float* erow = g_E + ((size_t)b * DD + d0 + ty * 8 + i) * 128 + tx * 8;
        *(float4*)&erow[0] = *(float4*)&acc[i][0];
        *(float4*)&erow[4] = *(float4*)&acc[i][4];
    }
}

__global__ void __launch_bounds__(256) k_weffT(const float* __restrict__ W, int b0) {
    int b = blockIdx.z + b0, o0 = blockIdx.y * 128, d0 = blockIdx.x * 128;
    __shared__ __align__(16) float As[16][132];
    __shared__ __align__(16) float Bs[16][132];
    int tid = threadIdx.x, tx = tid & 15, ty = tid >> 4;
    const float* Eb = g_E + (size_t)b * DD * 128;
    float acc[8][8] = {};
    int ar = tid >> 2, ac = (tid & 3) * 4;
    for (int k0 = 0; k0 < 128; k0 += 16) {
        #pragma unroll
        for (int i2 = 0; i2 < 2; i2++) {
            int idx = tid + i2 * 256;
            int r = idx >> 5, cc = (idx & 31) * 4;
            *(float4*)&As[r][cc] = *(const float4*)(g_T0 + (size_t)(k0 + r) * OUTD + o0 + cc);
        }
        #pragma unroll
        for (int h = 0; h < 2; h++) {
            int d = d0 + ar + h * 64;
            float4 v = *(const float4*)(Eb + (size_t)d * 128 + k0 + ac);
            Bs[ac + 0][ar + h * 64] = v.x;
            Bs[ac + 1][ar + h * 64] = v.y;
            Bs[ac + 2][ar + h * 64] = v.z;
            Bs[ac + 3][ar + h * 64] = v.w;
        }
        __syncthreads();
        #pragma unroll
        for (int kk = 0; kk < 16; kk++) {
            float av[8], bv[8];
            *(float4*)&av[0] = *(const float4*)&As[kk][ty * 8];
            *(float4*)&av[4] = *(const float4*)&As[kk][ty * 8 + 4];
            *(float4*)&bv[0] = *(const float4*)&Bs[kk][tx * 8];
            *(float4*)&bv[4] = *(const float4*)&Bs[kk][tx * 8 + 4];
            #pragma unroll
            for (int i = 0; i < 8; i++)
                #pragma unroll
                for (int j = 0; j < 8; j++) acc[i][j] += av[i] * bv[j];
        }
        __syncthreads();
    }
    float g = g_g2[b];
    #pragma unroll
    for (int i = 0; i < 8; i++) {
        int o = o0 + ty * 8 + i;
        const float* wrow = W + (size_t)o * DD + d0 + tx * 8;
        __align__(16) __half hb[8];
        #pragma unroll
        for (int j = 0; j < 8; j++)
            hb[j] = __float2half(wrow[j] + g * acc[i][j]);
        *(uint4*)(g_WTh + ((size_t)b * OUTD + o) * DD + d0 + tx * 8) = *(uint4*)hb;
    }
}

__global__ void k_lm(const float* __restrict__ x, const float* __restrict__ ker, int b0) {
    int by = blockIdx.x;
    int b = (by >> 5) + b0, y = by & 31, d = threadIdx.x;
    const float* xb = x + (size_t)b * NN * DD + d;
    float lg = g_lg[b];
    if (y == 0) g_lmh[(size_t)b * NN * DD + d] = __float2half(xb[0]);
    float k00 = ker[d * 9 + 0], k01 = ker[d * 9 + 1], k02 = ker[d * 9 + 2];
    float k10 = ker[d * 9 + 3], k11 = ker[d * 9 + 4], k12 = ker[d * 9 + 5];
    float k20 = ker[d * 9 + 6], k21 = ker[d * 9 + 7], k22 = ker[d * 9 + 8];
    bool up = (y > 0), dn = (y < 31);
    float ua = 0.f, ma = 0.f, la = 0.f, ub, mb, mc, lb, uc, lc;
    ub = up ? xb[(size_t)(1 + (y - 1) * 32) * DD] : 0.f;
    mb = xb[(size_t)(1 + y * 32) * DD];
    lb = dn ? xb[(size_t)(1 + (y + 1) * 32) * DD] : 0.f;
    for (int xx = 0; xx < 32; xx++) {
        if (xx < 31) {
            uc = up ? xb[(size_t)(1 + (y - 1) * 32 + xx + 1) * DD] : 0.f;
            mc = xb[(size_t)(1 + y * 32 + xx + 1) * DD];
            lc = dn ? xb[(size_t)(1 + (y + 1) * 32 + xx + 1) * DD] : 0.f;
        } else { uc = mc = lc = 0.f; }
        float conv = ua * k00 + ub * k01 + uc * k02 + ma * k10 + mb * k11 + mc * k12
                   + la * k20 + lb * k21 + lc * k22;
        float v = mb + lg * (conv - mb);
        g_lmh[((size_t)b * NN + 1 + y * 32 + xx) * DD + d] = __float2half(v);
        ua = ub; ub = uc; ma = mb; mb = mc; la = lb; lb = lc;
    }
}

// ---- main GEMM: 128x128 tiles, BK=64, 2-stage, grid y=9, batch offset ----
#define BK 64
#define ROWB 144
#define TILEB (128 * ROWB)       // 18432
#define STAGEB (2 * TILEB)       // 36864
#define NCH 6
#define GEMM_SMEM (2 * STAGEB)   // 73728

__device__ __forceinline__ void cp16(uint32_t dst, const void* src) {
    asm volatile("cp.async.cg.shared.global [%0], [%1], 16;" :: "r"(dst), "l"(src) : "memory");
}

__global__ void __launch_bounds__(256, 2) k_gemm_mma(const float* __restrict__ bias,
                                                     float* __restrict__ out, int b0) {
    extern __shared__ __align__(16) unsigned char sm[];
    __shared__ float s_bias[128], s_scale[128];
    int b = blockIdx.z + b0, m0 = blockIdx.y * 128, n0 = blockIdx.x * 128;
    int tid = threadIdx.x, lane = tid & 31, wid = tid >> 5;
    int wm = wid & 1, wn = wid >> 1;

    if (tid < 128) {
        s_bias[tid] = bias[n0 + tid];
        s_scale[tid] = g_scale[b * OUTD + n0 + tid];
    }

    uint32_t smb = smem_u32(sm);
    float acc[4][4][4];
    #pragma unroll
    for (int i = 0; i < 4; i++)
        #pragma unroll
        for (int j = 0; j < 4; j++)
            #pragma unroll
            for (int q = 0; q < 4; q++) acc[i][j][q] = 0.f;

    int rbase = tid >> 3, cc = tid & 7;      // 4 rows per thread: rbase+32q
    size_t aoff[4], boff[4];
    #pragma unroll
    for (int q = 0; q < 4; q++) {
        int am = m0 + rbase + 32 * q; if (am > NN - 1) am = NN - 1;
        aoff[q] = ((size_t)b * NN + am) * DD;
        boff[q] = ((size_t)b * OUTD + n0 + rbase + 32 * q) * DD;
    }

    #define LOAD_CHUNK(c, s) do { \
        int k0 = (c) * BK; \
        uint32_t Ax = smb + (uint32_t)(s) * STAGEB; \
        uint32_t Bh = Ax + TILEB; \
        _Pragma("unroll") \
        for (int q = 0; q < 4; q++) { \
            cp16(Ax + (rbase + 32 * q) * ROWB + cc * 16, g_lmh + aoff[q] + k0 + cc * 8); \
            cp16(Bh + (rbase + 32 * q) * ROWB + cc * 16, g_WTh + boff[q] + k0 + cc * 8); \
        } \
    } while (0)

    #define LDMA(dst, base, mf) do { \
        uint32_t addr = (base) + (uint32_t)((wm * 64 + (mf) * 16 + (lane & 15)) * ROWB \
                      + (kstep * 2 + (lane >> 4)) * 16); \
        asm volatile("ldmatrix.sync.aligned.m8n8.x4.shared.b16 {%0,%1,%2,%3}, [%4];" \
            : "=r"((dst)[0]), "=r"((dst)[1]), "=r"((dst)[2]), "=r"((dst)[3]) : "r"(addr)); \
    } while (0)

    #define LDMB(dst, base) do { \
        int g = lane >> 3; \
        _Pragma("unroll") \
        for (int nf2 = 0; nf2 < 2; nf2++) { \
            uint32_t addr = (base) + (uint32_t)((wn * 32 + nf2 * 16 + ((g >> 1) << 3) + (lane & 7)) * ROWB \
                          + (kstep * 2 + (g & 1)) * 16); \
            uint32_t q0, q1, q2, q3; \
            asm volatile("ldmatrix.sync.aligned.m8n8.x4.shared.b16 {%0,%1,%2,%3}, [%4];" \
                : "=r"(q0), "=r"(q1), "=r"(q2), "=r"(q3) : "r"(addr)); \
            (dst)[nf2 * 2][0] = q0; (dst)[nf2 * 2][1] = q1; \
            (dst)[nf2 * 2 + 1][0] = q2; (dst)[nf2 * 2 + 1][1] = q3; \
        } \
    } while (0)

    #define MMAS(af, bfr) do { \
        _Pragma("unroll") \
        for (int mf = 0; mf < 4; mf++) \
            _Pragma("unroll") \
            for (int nf = 0; nf < 4; nf++) { \
                asm volatile( \
                    "mma.sync.aligned.m16n8k16.row.col.f32.f16.f16.f32 " \
                    "{%0,%1,%2,%3}, {%4,%5,%6,%7}, {%8,%9}, {%0,%1,%2,%3};" \
                    : "+f"(acc[mf][nf][0]), "+f"(acc[mf][nf][1]), \
                      "+f"(acc[mf][nf][2]), "+f"(acc[mf][nf][3]) \
                    : "r"((af)[mf][0]), "r"((af)[mf][1]), "r"((af)[mf][2]), "r"((af)[mf][3]), \
                      "r"((bfr)[nf][0]), "r"((bfr)[nf][1])); \
            } \
    } while (0)

    LOAD_CHUNK(0, 0);
    asm volatile("cp.async.commit_group;" ::: "memory");

    for (int c = 0; c < NCH; c++) {
        if (c + 1 < NCH) {
            LOAD_CHUNK(c + 1, (c + 1) & 1);
            asm volatile("cp.async.commit_group;" ::: "memory");
            asm volatile("cp.async.wait_group 1;" ::: "memory");
        } else {
            asm volatile("cp.async.wait_group 0;" ::: "memory");
        }
        __syncthreads();

        uint32_t Ax = smb + (uint32_t)(c & 1) * STAGEB;
        uint32_t Bh = Ax + TILEB;
        #pragma unroll
        for (int kstep = 0; kstep < 4; kstep++) {
            uint32_t ah[4][4], bh[4][2];
            #pragma unroll
            for (int mf = 0; mf < 4; mf++) LDMA(ah[mf], Ax, mf);
            LDMB(bh, Bh);
            MMAS(ah, bh);
        }
        __syncthreads();
    }

    int gr = lane >> 2, gc = (lane & 3) * 2;
    #pragma unroll
    for (int mf = 0; mf < 4; mf++) {
        #pragma unroll
        for (int nf = 0; nf < 4; nf++) {
            int nl = wn * 32 + nf * 8 + gc;
            float b0f = s_bias[nl], b1f = s_bias[nl + 1];
            float sc0 = s_scale[nl], sc1 = s_scale[nl + 1];
            int mrow = m0 + wm * 64 + mf * 16 + gr;
            if (mrow < NN) {
                float2 v0 = make_float2((acc[mf][nf][0] + b0f) * sc0, (acc[mf][nf][1] + b1f) * sc1);
                *(float2*)(out + ((size_t)b * NN + mrow) * OUTD + n0 + nl) = v0;
            }
            if (mrow + 8 < NN) {
                float2 v1 = make_float2((acc[mf][nf][2] + b0f) * sc0, (acc[mf][nf][3] + b1f) * sc1);
                *(float2*)(out + ((size_t)b * NN + mrow + 8) * OUTD + n0 + nl) = v1;
            }
        }
    }
}

// ---------------- launch: fork-join + batch-split pipelining ----------------
static cudaStream_t s1, s2, s3;
static cudaEvent_t ev_fork, ev_prep, ev_PT0, ev_ctrl, ev_lmA, ev_lmB, ev_wA, ev_gA;

extern "C" void kernel_launch(void* const* d_in, const int* in_sizes, int n_in,
                              void* d_out, int out_size) {
    const float* x      = (const float*)d_in[0];
    const float* W      = (const float*)d_in[1];
    const float* bias   = (const float*)d_in[2];
    const float* Lb     = (const float*)d_in[3];
    const float* Rb     = (const float*)d_in[4];
    const float* sbasis = (const float*)d_in[5];
    const float* ss     = (const float*)d_in[6];
    const float* dwk    = (const float*)d_in[7];
    const float* w1     = (const float*)d_in[8];
    const float* b1     = (const float*)d_in[9];
    const float* w_rot  = (const float*)d_in[10];
    const float* b_rot  = (const float*)d_in[11];
    const float* w_rg   = (const float*)d_in[12];
    const float* b_rg   = (const float*)d_in[13];
    const float* w_lg   = (const float*)d_in[14];
    const float* b_lg   = (const float*)d_in[15];
    const float* w_sc   = (const float*)d_in[16];
    const float* b_sc   = (const float*)d_in[17];
    float* out = (float*)d_out;

    static int init_done = 0;
    if (!init_done) {
        cudaFuncSetAttribute(k_lusolve, cudaFuncAttributeMaxDynamicSharedMemorySize, LUSOLVE_SMEM);
        cudaFuncSetAttribute(k_gemm_mma, cudaFuncAttributeMaxDynamicSharedMemorySize, GEMM_SMEM);
        cudaStreamCreateWithFlags(&s1, cudaStreamNonBlocking);
        cudaStreamCreateWithFlags(&s2, cudaStreamNonBlocking);
        cudaStreamCreateWithFlags(&s3, cudaStreamNonBlocking);
        cudaEventCreateWithFlags(&ev_fork, cudaEventDisableTiming);
        cudaEventCreateWithFlags(&ev_prep, cudaEventDisableTiming);
        cudaEventCreateWithFlags(&ev_PT0, cudaEventDisableTiming);
        cudaEventCreateWithFlags(&ev_ctrl, cudaEventDisableTiming);
        cudaEventCreateWithFlags(&ev_lmA, cudaEventDisableTiming);
        cudaEventCreateWithFlags(&ev_lmB, cudaEventDisableTiming);
        cudaEventCreateWithFlags(&ev_wA, cudaEventDisableTiming);
        cudaEventCreateWithFlags(&ev_gA, cudaEventDisableTiming);
        init_done = 1;
    }

    cudaEventRecord(ev_fork, 0);
    cudaStreamWaitEvent(s1, ev_fork, 0);
    cudaStreamWaitEvent(s2, ev_fork, 0);
    cudaStreamWaitEvent(s3, ev_fork, 0);

    // s1: basis chain
    k_prep<<<200, 256, 0, s1>>>(Lb, Rb);
    cudaEventRecord(ev_prep, s1);
    k_PT0<<<16, 256, 0, s1>>>(W);
    cudaEventRecord(ev_PT0, s1);

    // origin (0): stats -> ctrl
    k_stats<<<dim3(BB, NSC), 384>>>(x);
    cudaStreamWaitEvent(0, ev_prep, 0);
    k_ctrl<<<BB, 512>>>(w1, b1, w_rot, b_rot, w_rg, b_rg, w_lg, b_lg, w_sc, b_sc, sbasis, ss);
    cudaEventRecord(ev_ctrl, 0);

    // s2: lm halves (need ctrl)
    cudaStreamWaitEvent(s2, ev_ctrl, 0);
    k_lm<<<32 * 32, 384, 0, s2>>>(x, dwk, 0);
    cudaEventRecord(ev_lmA, s2);
    k_lm<<<32 * 32, 384, 0, s2>>>(x, dwk, 32);
    cudaEventRecord(ev_lmB, s2);

    // origin: solve chain -> weffT halves
    cudaStreamWaitEvent(0, ev_PT0, 0);
    k_lusolve<<<BB, 128, LUSOLVE_SMEM>>>();
    k_E<<<dim3(1, 3, BB), 256>>>();
    k_weffT<<<dim3(3, 3, 32), 256>>>(W, 0);
    cudaEventRecord(ev_wA, 0);

    // s3: gemm_A as soon as its inputs are ready
    cudaStreamWaitEvent(s3, ev_wA, 0);
    cudaStreamWaitEvent(s3, ev_lmA, 0);
    k_gemm_mma<<<dim3(3, 9, 32), 256, GEMM_SMEM, s3>>>(bias, out, 0);
    cudaEventRecord(ev_gA, s3);

    // origin: weffT_B -> gemm_B
    k_weffT<<<dim3(3, 3, 32), 256>>>(W, 32);
    cudaStreamWaitEvent(0, ev_lmB, 0);
    k_gemm_mma<<<dim3(3, 9, 32), 256, GEMM_SMEM>>>(bias, out, 32);

    // join gemm_A back into origin
    cudaStreamWaitEvent(0, ev_gA, 0);
}